// round 1
// baseline (speedup 1.0000x reference)
#include <cuda_runtime.h>
#include <math.h>

#define D_MODEL 768
#define RANK 4
#define BATCH 2
#define TLEN 2048
#define MROWS (BATCH*TLEN)          // 4096
#define N1 (D_MODEL*RANK*2)         // 6144
#define KD D_MODEL                  // 768
#define NCH (D_MODEL*RANK)          // 3072 complex channels per batch
#define NCHUNK 16
#define CL (TLEN/NCHUNK)            // 128

// ---------------- scratch (static __device__, no allocations) ----------------
__device__ float  g_xn[MROWS*KD];           // 12.6 MB  normalized input
__device__ float  g_u [MROWS*N1];           // 96  MB  GEMM1 output (u interleaved re/im)
__device__ float  g_y [MROWS*D_MODEL];      // 12.6 MB  scan output
__device__ float2 g_ca[NCH], g_cb[NCH], g_cc[NCH], g_aL[NCH];
__device__ float2 g_Sloc [BATCH*NCHUNK*NCH];
__device__ float2 g_carry[BATCH*NCHUNK*NCH];

// ---------------- coefficient precompute ----------------
__global__ void coef_kernel(const float* __restrict__ ap,
                            const float* __restrict__ bp,
                            const float* __restrict__ cp) {
    int i = blockIdx.x * blockDim.x + threadIdx.x;
    if (i >= NCH) return;
    float2 a = make_float2(tanhf(ap[2*i]) * 0.97f, tanhf(ap[2*i+1]) * 0.97f);
    float2 b = make_float2(tanhf(bp[2*i]),         tanhf(bp[2*i+1]));
    float2 c = make_float2(tanhf(cp[2*i]),         tanhf(cp[2*i+1]));
    g_ca[i] = a; g_cb[i] = b; g_cc[i] = c;
    // aL = a^CL
    float2 p = a;
    for (int k = 1; k < CL; ++k)
        p = make_float2(p.x*a.x - p.y*a.y, p.x*a.y + p.y*a.x);
    g_aL[i] = p;
}

// ---------------- RMSNorm ----------------
__global__ void rmsnorm_kernel(const float* __restrict__ x,
                               const float* __restrict__ w) {
    int row = blockIdx.x;
    const float* xr = x + (size_t)row * KD;
    float* o = g_xn + (size_t)row * KD;
    float s = 0.f;
    for (int k = threadIdx.x; k < KD; k += 256) { float v = xr[k]; s += v * v; }
    __shared__ float red[256];
    red[threadIdx.x] = s; __syncthreads();
    for (int off = 128; off > 0; off >>= 1) {
        if (threadIdx.x < off) red[threadIdx.x] += red[threadIdx.x + off];
        __syncthreads();
    }
    float scale = rsqrtf(red[0] * (1.0f / KD) + 1e-6f);
    for (int k = threadIdx.x; k < KD; k += 256) o[k] = xr[k] * scale * w[k];
}

// ---------------- fp32 SIMT GEMM:  C[M,N] = A[M,K] * B[N,K]^T  (all row-major) ----------------
// M%128==0, N%128==0, K%8==0. 256 threads, 128x128 block tile, 8x8 per thread.
__device__ __forceinline__ void sgemm_nt(const float* __restrict__ A,
                                         const float* __restrict__ Bm,
                                         float* __restrict__ C,
                                         int M, int N, int K) {
    __shared__ float As[8][128];
    __shared__ float Bs[8][128];
    int tid  = threadIdx.x;
    int bm   = blockIdx.y * 128;
    int bn   = blockIdx.x * 128;
    int lrow = tid >> 1;            // 0..127
    int lc   = (tid & 1) * 4;       // 0 or 4
    const float* Ap = A  + (size_t)(bm + lrow) * K + lc;
    const float* Bp = Bm + (size_t)(bn + lrow) * K + lc;
    int tx = tid & 15, ty = tid >> 4;

    float acc[8][8];
#pragma unroll
    for (int i = 0; i < 8; ++i)
#pragma unroll
        for (int j = 0; j < 8; ++j) acc[i][j] = 0.f;

    float4 av = *(const float4*)Ap;
    float4 bv = *(const float4*)Bp;
    int nt = K / 8;
    for (int t = 0; t < nt; ++t) {
        As[lc+0][lrow] = av.x; As[lc+1][lrow] = av.y;
        As[lc+2][lrow] = av.z; As[lc+3][lrow] = av.w;
        Bs[lc+0][lrow] = bv.x; Bs[lc+1][lrow] = bv.y;
        Bs[lc+2][lrow] = bv.z; Bs[lc+3][lrow] = bv.w;
        __syncthreads();
        if (t + 1 < nt) {
            av = *(const float4*)(Ap + (t + 1) * 8);
            bv = *(const float4*)(Bp + (t + 1) * 8);
        }
#pragma unroll
        for (int kk = 0; kk < 8; ++kk) {
            float4 a0 = *(const float4*)&As[kk][ty * 8];
            float4 a1 = *(const float4*)&As[kk][ty * 8 + 4];
            float4 b0 = *(const float4*)&Bs[kk][tx * 8];
            float4 b1 = *(const float4*)&Bs[kk][tx * 8 + 4];
            float ar[8] = {a0.x,a0.y,a0.z,a0.w,a1.x,a1.y,a1.z,a1.w};
            float br[8] = {b0.x,b0.y,b0.z,b0.w,b1.x,b1.y,b1.z,b1.w};
#pragma unroll
            for (int i = 0; i < 8; ++i)
#pragma unroll
                for (int j = 0; j < 8; ++j)
                    acc[i][j] = fmaf(ar[i], br[j], acc[i][j]);
        }
        __syncthreads();
    }
#pragma unroll
    for (int i = 0; i < 8; ++i) {
        int row = bm + ty * 8 + i;
        float* cp = C + (size_t)row * N + bn + tx * 8;
        *(float4*)cp       = make_float4(acc[i][0], acc[i][1], acc[i][2], acc[i][3]);
        *(float4*)(cp + 4) = make_float4(acc[i][4], acc[i][5], acc[i][6], acc[i][7]);
    }
}

__global__ __launch_bounds__(256, 2) void gemm1_kernel(const float* __restrict__ Win) {
    sgemm_nt(g_xn, Win, g_u, MROWS, N1, KD);
}
__global__ __launch_bounds__(256, 2) void gemm2_kernel(const float* __restrict__ Wout,
                                                       float* __restrict__ out) {
    sgemm_nt(g_y, Wout, out, MROWS, D_MODEL, KD);
}

// ---------------- Phase A: per-chunk local scan from zero state ----------------
// grid (D_MODEL/256, NCHUNK, BATCH); one thread per d, 4 complex states in regs.
__global__ void scanA_kernel() {
    int d = blockIdx.x * 256 + threadIdx.x;    // 0..767
    int j = blockIdx.y, b = blockIdx.z;
    int ch0 = d * RANK;
    float2 a[RANK], bb[RANK], cc[RANK], s[RANK];
#pragma unroll
    for (int r = 0; r < RANK; ++r) {
        a[r] = g_ca[ch0 + r]; bb[r] = g_cb[ch0 + r]; cc[r] = g_cc[ch0 + r];
        s[r] = make_float2(0.f, 0.f);
    }
    int t0 = j * CL;
    const float4* up = (const float4*)(g_u + (size_t)(b * TLEN + t0) * N1 + d * (RANK * 2));
    float* yp = g_y + (size_t)(b * TLEN + t0) * D_MODEL + d;
    for (int t = 0; t < CL; ++t) {
        float4 u0 = up[0], u1 = up[1];
        float ur[4] = {u0.x, u0.z, u1.x, u1.z};
        float ui[4] = {u0.y, u0.w, u1.y, u1.w};
        float y = 0.f;
#pragma unroll
        for (int r = 0; r < RANK; ++r) {
            float bur = bb[r].x * ur[r] - bb[r].y * ui[r];
            float bui = bb[r].x * ui[r] + bb[r].y * ur[r];
            float sr  = a[r].x * s[r].x - a[r].y * s[r].y + bur;
            float si  = a[r].x * s[r].y + a[r].y * s[r].x + bui;
            s[r] = make_float2(sr, si);
            y += cc[r].x * sr - cc[r].y * si;
        }
        *yp = y;
        up += N1 / 4;
        yp += D_MODEL;
    }
    float2* sp = g_Sloc + (size_t)(b * NCHUNK + j) * NCH + ch0;
#pragma unroll
    for (int r = 0; r < RANK; ++r) sp[r] = s[r];
}

// ---------------- Phase B: sequential carry combine across chunks (tiny) ----------------
__global__ void scanB_kernel() {
    int idx = blockIdx.x * 256 + threadIdx.x;
    if (idx >= BATCH * NCH) return;
    int b = idx / NCH, ch = idx % NCH;
    float2 aL = g_aL[ch];
    float2 carry = make_float2(0.f, 0.f);
    for (int j = 0; j < NCHUNK; ++j) {
        g_carry[(size_t)(b * NCHUNK + j) * NCH + ch] = carry;
        float2 S = g_Sloc[(size_t)(b * NCHUNK + j) * NCH + ch];
        carry = make_float2(aL.x * carry.x - aL.y * carry.y + S.x,
                            aL.x * carry.y + aL.y * carry.x + S.y);
    }
}

// ---------------- Phase C: closed-form carry correction, y += Re(c * a^p * carry) ----------------
// grid (D_MODEL/256, NCHUNK-1, BATCH); chunk j=0 has zero carry -> skipped.
__global__ void scanC_kernel() {
    int d = blockIdx.x * 256 + threadIdx.x;
    int j = blockIdx.y + 1, b = blockIdx.z;
    int ch0 = d * RANK;
    float2 a[RANK], w[RANK];
#pragma unroll
    for (int r = 0; r < RANK; ++r) {
        a[r] = g_ca[ch0 + r];
        float2 carry = g_carry[(size_t)(b * NCHUNK + j) * NCH + ch0 + r];
        float2 c = g_cc[ch0 + r];
        w[r] = make_float2(c.x * carry.x - c.y * carry.y,
                           c.x * carry.y + c.y * carry.x);
    }
    int t0 = j * CL;
    float* yp = g_y + (size_t)(b * TLEN + t0) * D_MODEL + d;
    for (int t = 0; t < CL; ++t) {
        float corr = 0.f;
#pragma unroll
        for (int r = 0; r < RANK; ++r) {
            w[r] = make_float2(w[r].x * a[r].x - w[r].y * a[r].y,
                               w[r].x * a[r].y + w[r].y * a[r].x);
            corr += w[r].x;
        }
        *yp += corr;
        yp += D_MODEL;
    }
}

// ---------------- launch ----------------
extern "C" void kernel_launch(void* const* d_in, const int* in_sizes, int n_in,
                              void* d_out, int out_size) {
    const float* x    = (const float*)d_in[0];
    const float* nw   = (const float*)d_in[1];
    const float* Win  = (const float*)d_in[2];
    const float* Wout = (const float*)d_in[3];
    const float* ap   = (const float*)d_in[4];
    const float* bp   = (const float*)d_in[5];
    const float* cp   = (const float*)d_in[6];
    float* out = (float*)d_out;

    coef_kernel<<<(NCH + 255) / 256, 256>>>(ap, bp, cp);
    rmsnorm_kernel<<<MROWS, 256>>>(x, nw);
    gemm1_kernel<<<dim3(N1 / 128, MROWS / 128), 256>>>(Win);
    scanA_kernel<<<dim3(D_MODEL / 256, NCHUNK, BATCH), 256>>>();
    scanB_kernel<<<(BATCH * NCH + 255) / 256, 256>>>();
    scanC_kernel<<<dim3(D_MODEL / 256, NCHUNK - 1, BATCH), 256>>>();
    gemm2_kernel<<<dim3(D_MODEL / 128, MROWS / 128), 256>>>(Wout, out);
}

// round 6
// speedup vs baseline: 1.7485x; 1.7485x over previous
#include <cuda_runtime.h>
#include <cuda_bf16.h>
#include <math.h>
#include <stdint.h>

#define D_MODEL 768
#define RANK 4
#define BATCH 2
#define TLEN 2048
#define MROWS (BATCH*TLEN)          // 4096
#define N1 (D_MODEL*RANK*2)         // 6144
#define KD D_MODEL                  // 768
#define NCH (D_MODEL*RANK)          // 3072
#define NCHUNK 128
#define CL (TLEN/NCHUNK)            // 16

// ---------------- scratch (static __device__, no allocations) ----------------
__device__ __nv_bfloat16 g_xh [MROWS*KD], g_xl [MROWS*KD];
__device__ __nv_bfloat16 g_wih[N1*KD],    g_wil[N1*KD];
__device__ __nv_bfloat16 g_woh[KD*KD],    g_wol[KD*KD];
__device__ __nv_bfloat16 g_yh [MROWS*KD], g_yl [MROWS*KD];
__device__ float  g_u[MROWS*N1];
__device__ float  g_y[MROWS*KD];
__device__ float2 g_ca[NCH], g_cb[NCH], g_cc[NCH], g_aL[NCH];
__device__ float2 g_Sloc [BATCH*NCHUNK*NCH];
__device__ float2 g_carry[BATCH*NCHUNK*NCH];

// ---------------- coefficient precompute ----------------
__global__ void coef_kernel(const float* __restrict__ ap,
                            const float* __restrict__ bp,
                            const float* __restrict__ cp) {
    int i = blockIdx.x * blockDim.x + threadIdx.x;
    if (i >= NCH) return;
    float2 a = make_float2(tanhf(ap[2*i]) * 0.97f, tanhf(ap[2*i+1]) * 0.97f);
    float2 b = make_float2(tanhf(bp[2*i]),         tanhf(bp[2*i+1]));
    float2 c = make_float2(tanhf(cp[2*i]),         tanhf(cp[2*i+1]));
    g_ca[i] = a; g_cb[i] = b; g_cc[i] = c;
    float2 p = a;
    for (int k = 1; k < CL; ++k)
        p = make_float2(p.x*a.x - p.y*a.y, p.x*a.y + p.y*a.x);
    g_aL[i] = p;
}

// ---------------- bf16 hi/lo splits (globals referenced in DEVICE code) ------
__device__ __forceinline__ void split1(float v, __nv_bfloat16& h, __nv_bfloat16& l) {
    h = __float2bfloat16(v);
    l = __float2bfloat16(v - __bfloat162float(h));
}
__global__ void split_win_kernel(const float* __restrict__ w) {
    int i = blockIdx.x * 256 + threadIdx.x;
    if (i < N1*KD) split1(w[i], g_wih[i], g_wil[i]);
}
__global__ void split_wout_kernel(const float* __restrict__ w) {
    int i = blockIdx.x * 256 + threadIdx.x;
    if (i < KD*KD) split1(w[i], g_woh[i], g_wol[i]);
}
__global__ void split_y_kernel() {
    int i = blockIdx.x * 256 + threadIdx.x;
    if (i < MROWS*KD) split1(g_y[i], g_yh[i], g_yl[i]);
}

// ---------------- RMSNorm -> bf16 hi/lo ----------------
__global__ void rmsnorm_kernel(const float* __restrict__ x,
                               const float* __restrict__ w) {
    int row = blockIdx.x;
    const float* xr = x + (size_t)row * KD;
    float s = 0.f;
    for (int k = threadIdx.x; k < KD; k += 256) { float v = xr[k]; s += v * v; }
    __shared__ float red[256];
    red[threadIdx.x] = s; __syncthreads();
    for (int off = 128; off > 0; off >>= 1) {
        if (threadIdx.x < off) red[threadIdx.x] += red[threadIdx.x + off];
        __syncthreads();
    }
    float scale = rsqrtf(red[0] * (1.0f / KD) + 1e-6f);
    for (int k = threadIdx.x; k < KD; k += 256)
        split1(xr[k] * scale * w[k], g_xh[(size_t)row*KD + k], g_xl[(size_t)row*KD + k]);
}

// ============================================================================
// bf16-split tensor GEMM:  C[M,N] = (Ah+Al)[M,K] * (Bh+Bl)[N,K]^T, fp32 accum.
// BM=BN=128, BK=32, 256 threads, warp grid 2x4, warp tile 64x32,
// mma.m16n8k16.bf16, plain ld/st single-buffered smem (40KB static).
// Device function + device-side symbol binding in wrappers (R1-proven pattern).
// ============================================================================
#define SRW 40   // smem row stride in bf16 (80B)

__device__ __forceinline__ void mma_bf16(float* c, const uint32_t* a,
                                         uint32_t b0, uint32_t b1) {
    asm volatile(
        "mma.sync.aligned.m16n8k16.row.col.f32.bf16.bf16.f32 "
        "{%0,%1,%2,%3}, {%4,%5,%6,%7}, {%8,%9}, {%0,%1,%2,%3};\n"
        : "+f"(c[0]), "+f"(c[1]), "+f"(c[2]), "+f"(c[3])
        : "r"(a[0]), "r"(a[1]), "r"(a[2]), "r"(a[3]), "r"(b0), "r"(b1));
}

__device__ __forceinline__ void gemm_bf16s(
    const __nv_bfloat16* __restrict__ Ah, const __nv_bfloat16* __restrict__ Al,
    const __nv_bfloat16* __restrict__ Bh, const __nv_bfloat16* __restrict__ Bl,
    float* __restrict__ C, int N, int K)
{
    __shared__ __nv_bfloat16 sm[4 * 128 * SRW];   // 40960 bytes
    __nv_bfloat16* sAh = sm;
    __nv_bfloat16* sAl = sm + 128 * SRW;
    __nv_bfloat16* sBh = sm + 2 * 128 * SRW;
    __nv_bfloat16* sBl = sm + 3 * 128 * SRW;

    int tid  = threadIdx.x;
    int bm   = blockIdx.y * 128;
    int bn   = blockIdx.x * 128;
    int warp = tid >> 5, lane = tid & 31;
    int wm   = (warp & 1) * 64;
    int wn   = (warp >> 1) * 32;
    int g    = lane >> 2, tg = lane & 3;

    float acc[4][4][4];
#pragma unroll
    for (int i = 0; i < 4; ++i)
#pragma unroll
        for (int j = 0; j < 4; ++j)
#pragma unroll
            for (int v = 0; v < 4; ++v) acc[i][j][v] = 0.f;

    int row  = tid >> 1;             // 0..127
    int half = (tid & 1) * 16;       // bf16 offset within 32-wide tile row
    const __nv_bfloat16* gAh = Ah + (size_t)(bm + row) * K + half;
    const __nv_bfloat16* gAl = Al + (size_t)(bm + row) * K + half;
    const __nv_bfloat16* gBh = Bh + (size_t)(bn + row) * K + half;
    const __nv_bfloat16* gBl = Bl + (size_t)(bn + row) * K + half;
    int sidx = row * SRW + half;

    int nt = K / 32;                 // 24
    for (int t = 0; t < nt; ++t) {
        int k0 = t * 32;
        uint4 a0 = *(const uint4*)(gAh + k0);
        uint4 a1 = *(const uint4*)(gAh + k0 + 8);
        uint4 l0 = *(const uint4*)(gAl + k0);
        uint4 l1 = *(const uint4*)(gAl + k0 + 8);
        uint4 b0 = *(const uint4*)(gBh + k0);
        uint4 b1 = *(const uint4*)(gBh + k0 + 8);
        uint4 c0 = *(const uint4*)(gBl + k0);
        uint4 c1 = *(const uint4*)(gBl + k0 + 8);
        __syncthreads();             // previous compute done before overwrite
        *(uint4*)(sAh + sidx)     = a0;  *(uint4*)(sAh + sidx + 8) = a1;
        *(uint4*)(sAl + sidx)     = l0;  *(uint4*)(sAl + sidx + 8) = l1;
        *(uint4*)(sBh + sidx)     = b0;  *(uint4*)(sBh + sidx + 8) = b1;
        *(uint4*)(sBl + sidx)     = c0;  *(uint4*)(sBl + sidx + 8) = c1;
        __syncthreads();

#pragma unroll
        for (int ks = 0; ks < 2; ++ks) {
            int kk = ks * 16 + 2 * tg;
            uint32_t ah[4][4], al[4][4];
#pragma unroll
            for (int i = 0; i < 4; ++i) {
                int r0 = wm + i * 16 + g;
                ah[i][0] = *(const uint32_t*)&sAh[ r0      * SRW + kk];
                ah[i][1] = *(const uint32_t*)&sAh[(r0 + 8) * SRW + kk];
                ah[i][2] = *(const uint32_t*)&sAh[ r0      * SRW + kk + 8];
                ah[i][3] = *(const uint32_t*)&sAh[(r0 + 8) * SRW + kk + 8];
                al[i][0] = *(const uint32_t*)&sAl[ r0      * SRW + kk];
                al[i][1] = *(const uint32_t*)&sAl[(r0 + 8) * SRW + kk];
                al[i][2] = *(const uint32_t*)&sAl[ r0      * SRW + kk + 8];
                al[i][3] = *(const uint32_t*)&sAl[(r0 + 8) * SRW + kk + 8];
            }
#pragma unroll
            for (int j = 0; j < 4; ++j) {
                int n0 = wn + j * 8 + g;
                uint32_t bh0 = *(const uint32_t*)&sBh[n0 * SRW + kk];
                uint32_t bh1 = *(const uint32_t*)&sBh[n0 * SRW + kk + 8];
                uint32_t bl0 = *(const uint32_t*)&sBl[n0 * SRW + kk];
                uint32_t bl1 = *(const uint32_t*)&sBl[n0 * SRW + kk + 8];
#pragma unroll
                for (int i = 0; i < 4; ++i) {
                    mma_bf16(acc[i][j], ah[i], bh0, bh1);   // hi*hi
                    mma_bf16(acc[i][j], al[i], bh0, bh1);   // lo*hi
                    mma_bf16(acc[i][j], ah[i], bl0, bl1);   // hi*lo
                }
            }
        }
    }

#pragma unroll
    for (int i = 0; i < 4; ++i) {
        int r0 = bm + wm + i * 16 + g;
#pragma unroll
        for (int j = 0; j < 4; ++j) {
            int col = bn + wn + j * 8 + tg * 2;
            *(float2*)(C + (size_t)r0      * N + col) = make_float2(acc[i][j][0], acc[i][j][1]);
            *(float2*)(C + (size_t)(r0+8)  * N + col) = make_float2(acc[i][j][2], acc[i][j][3]);
        }
    }
}

// wrappers bind device globals IN DEVICE CODE (the R1-proven pattern)
__global__ __launch_bounds__(256) void gemm1_kernel() {
    gemm_bf16s(g_xh, g_xl, g_wih, g_wil, g_u, N1, KD);
}
__global__ __launch_bounds__(256) void gemm2_kernel(float* __restrict__ out) {
    gemm_bf16s(g_yh, g_yl, g_woh, g_wol, out, KD, KD);
}

// ---------------- Phase A: per-chunk local scan from zero state ----------------
__global__ void scanA_kernel() {
    int d = blockIdx.x * 256 + threadIdx.x;
    int j = blockIdx.y, b = blockIdx.z;
    int ch0 = d * RANK;
    float2 a[RANK], bb[RANK], cc[RANK], s[RANK];
#pragma unroll
    for (int r = 0; r < RANK; ++r) {
        a[r] = g_ca[ch0 + r]; bb[r] = g_cb[ch0 + r]; cc[r] = g_cc[ch0 + r];
        s[r] = make_float2(0.f, 0.f);
    }
    int t0 = j * CL;
    const float4* up = (const float4*)(g_u + (size_t)(b * TLEN + t0) * N1 + d * (RANK * 2));
    float* yp = g_y + (size_t)(b * TLEN + t0) * D_MODEL + d;
    for (int t = 0; t < CL; ++t) {
        float4 u0 = up[0], u1 = up[1];
        float ur[4] = {u0.x, u0.z, u1.x, u1.z};
        float ui[4] = {u0.y, u0.w, u1.y, u1.w};
        float y = 0.f;
#pragma unroll
        for (int r = 0; r < RANK; ++r) {
            float bur = bb[r].x * ur[r] - bb[r].y * ui[r];
            float bui = bb[r].x * ui[r] + bb[r].y * ur[r];
            float sr  = a[r].x * s[r].x - a[r].y * s[r].y + bur;
            float si  = a[r].x * s[r].y + a[r].y * s[r].x + bui;
            s[r] = make_float2(sr, si);
            y += cc[r].x * sr - cc[r].y * si;
        }
        *yp = y;
        up += N1 / 4;
        yp += D_MODEL;
    }
    float2* sp = g_Sloc + (size_t)(b * NCHUNK + j) * NCH + ch0;
#pragma unroll
    for (int r = 0; r < RANK; ++r) sp[r] = s[r];
}

// ---------------- Phase B: sequential carry combine across chunks ----------------
__global__ void scanB_kernel() {
    int idx = blockIdx.x * 256 + threadIdx.x;
    if (idx >= BATCH * NCH) return;
    int b = idx / NCH, ch = idx % NCH;
    float2 aL = g_aL[ch];
    float2 carry = make_float2(0.f, 0.f);
    for (int j = 0; j < NCHUNK; ++j) {
        g_carry[(size_t)(b * NCHUNK + j) * NCH + ch] = carry;
        float2 S = g_Sloc[(size_t)(b * NCHUNK + j) * NCH + ch];
        carry = make_float2(aL.x * carry.x - aL.y * carry.y + S.x,
                            aL.x * carry.y + aL.y * carry.x + S.y);
    }
}

// ---------------- Phase C: y += Re(c * a^p * carry) ----------------
__global__ void scanC_kernel() {
    int d = blockIdx.x * 256 + threadIdx.x;
    int j = blockIdx.y + 1, b = blockIdx.z;
    int ch0 = d * RANK;
    float2 a[RANK], w[RANK];
#pragma unroll
    for (int r = 0; r < RANK; ++r) {
        a[r] = g_ca[ch0 + r];
        float2 carry = g_carry[(size_t)(b * NCHUNK + j) * NCH + ch0 + r];
        float2 c = g_cc[ch0 + r];
        w[r] = make_float2(c.x * carry.x - c.y * carry.y,
                           c.x * carry.y + c.y * carry.x);
    }
    int t0 = j * CL;
    float* yp = g_y + (size_t)(b * TLEN + t0) * D_MODEL + d;
    for (int t = 0; t < CL; ++t) {
        float corr = 0.f;
#pragma unroll
        for (int r = 0; r < RANK; ++r) {
            w[r] = make_float2(w[r].x * a[r].x - w[r].y * a[r].y,
                               w[r].x * a[r].y + w[r].y * a[r].x);
            corr += w[r].x;
        }
        *yp += corr;
        yp += D_MODEL;
    }
}

// ---------------- launch (NO device symbols passed from host) ----------------
extern "C" void kernel_launch(void* const* d_in, const int* in_sizes, int n_in,
                              void* d_out, int out_size) {
    const float* x    = (const float*)d_in[0];
    const float* nw   = (const float*)d_in[1];
    const float* Win  = (const float*)d_in[2];
    const float* Wout = (const float*)d_in[3];
    const float* ap   = (const float*)d_in[4];
    const float* bp   = (const float*)d_in[5];
    const float* cp   = (const float*)d_in[6];
    float* out = (float*)d_out;

    coef_kernel<<<(NCH + 255) / 256, 256>>>(ap, bp, cp);
    split_win_kernel<<<(N1 * KD + 255) / 256, 256>>>(Win);
    split_wout_kernel<<<(KD * KD + 255) / 256, 256>>>(Wout);
    rmsnorm_kernel<<<MROWS, 256>>>(x, nw);
    gemm1_kernel<<<dim3(N1 / 128, MROWS / 128), 256>>>();
    scanA_kernel<<<dim3(D_MODEL / 256, NCHUNK, BATCH), 256>>>();
    scanB_kernel<<<(BATCH * NCH + 255) / 256, 256>>>();
    scanC_kernel<<<dim3(D_MODEL / 256, NCHUNK - 1, BATCH), 256>>>();
    split_y_kernel<<<(MROWS * KD + 255) / 256, 256>>>();
    gemm2_kernel<<<dim3(KD / 128, MROWS / 128), 256>>>(out);
}

// round 8
// speedup vs baseline: 2.3436x; 1.3403x over previous
#include <cuda_runtime.h>
#include <cuda_fp16.h>
#include <math.h>
#include <stdint.h>

#define D_MODEL 768
#define RANK 4
#define BATCH 2
#define TLEN 2048
#define MROWS (BATCH*TLEN)          // 4096
#define N1 (D_MODEL*RANK*2)         // 6144
#define KD D_MODEL                  // 768
#define NCH (D_MODEL*RANK)          // 3072
#define NCHUNK 128
#define CL (TLEN/NCHUNK)            // 16

// ---------------- scratch (static __device__, no allocations) ----------------
__device__ __half g_xh [MROWS*KD], g_xl [MROWS*KD];   // x split hi/lo (fp16)
__device__ __half g_wih[N1*KD];                       // W_in  rounded fp16
__device__ __half g_woh[KD*KD];                       // W_out rounded fp16
__device__ __half g_yh [MROWS*KD], g_yl [MROWS*KD];   // y split hi/lo
__device__ float  g_u[MROWS*N1];
__device__ float  g_y[MROWS*KD];
__device__ float2 g_ca[NCH], g_cb[NCH], g_cc[NCH], g_aL[NCH];
__device__ float2 g_Sloc [BATCH*NCHUNK*NCH];
__device__ float2 g_carry[BATCH*NCHUNK*NCH];

// ---------------- coefficient precompute ----------------
__global__ void coef_kernel(const float* __restrict__ ap,
                            const float* __restrict__ bp,
                            const float* __restrict__ cp) {
    int i = blockIdx.x * blockDim.x + threadIdx.x;
    if (i >= NCH) return;
    float2 a = make_float2(tanhf(ap[2*i]) * 0.97f, tanhf(ap[2*i+1]) * 0.97f);
    float2 b = make_float2(tanhf(bp[2*i]),         tanhf(bp[2*i+1]));
    float2 c = make_float2(tanhf(cp[2*i]),         tanhf(cp[2*i+1]));
    g_ca[i] = a; g_cb[i] = b; g_cc[i] = c;
    float2 p = a;
    for (int k = 1; k < CL; ++k)
        p = make_float2(p.x*a.x - p.y*a.y, p.x*a.y + p.y*a.x);
    g_aL[i] = p;
}

// ---------------- fp16 rounding / splitting ----------------
__device__ __forceinline__ void split1(float v, __half& h, __half& l) {
    h = __float2half(v);
    l = __float2half(v - __half2float(h));
}
__global__ void round_win_kernel(const float* __restrict__ w) {
    int i = blockIdx.x * 256 + threadIdx.x;
    if (i < N1*KD) g_wih[i] = __float2half(w[i]);
}
__global__ void round_wout_kernel(const float* __restrict__ w) {
    int i = blockIdx.x * 256 + threadIdx.x;
    if (i < KD*KD) g_woh[i] = __float2half(w[i]);
}
__global__ void split_y_kernel() {
    int i = blockIdx.x * 256 + threadIdx.x;
    if (i < MROWS*KD) split1(g_y[i], g_yh[i], g_yl[i]);
}

// ---------------- RMSNorm -> fp16 hi/lo ----------------
__global__ void rmsnorm_kernel(const float* __restrict__ x,
                               const float* __restrict__ w) {
    int row = blockIdx.x;
    const float* xr = x + (size_t)row * KD;
    float s = 0.f;
    for (int k = threadIdx.x; k < KD; k += 256) { float v = xr[k]; s += v * v; }
    __shared__ float red[256];
    red[threadIdx.x] = s; __syncthreads();
    for (int off = 128; off > 0; off >>= 1) {
        if (threadIdx.x < off) red[threadIdx.x] += red[threadIdx.x + off];
        __syncthreads();
    }
    float scale = rsqrtf(red[0] * (1.0f / KD) + 1e-6f);
    for (int k = threadIdx.x; k < KD; k += 256)
        split1(xr[k] * scale * w[k], g_xh[(size_t)row*KD + k], g_xl[(size_t)row*KD + k]);
}

// ============================================================================
// fp16 2-term split GEMM:  C[M,N] = (Ah+Al)[M,K] * Bh[N,K]^T, fp32 accum.
// BM=BN=128, BK=32, 256 threads, warp grid 2x4, warp tile 64x32,
// mma.m16n8k16.f16.f32, register-prefetch pipelined smem (30KB static).
// Fragment indexing identical to the R5-proven bf16 kernel.
// ============================================================================
#define SRW 40   // smem row stride in fp16 (80B)

__device__ __forceinline__ void mma_f16(float* c, const uint32_t* a,
                                        uint32_t b0, uint32_t b1) {
    asm volatile(
        "mma.sync.aligned.m16n8k16.row.col.f32.f16.f16.f32 "
        "{%0,%1,%2,%3}, {%4,%5,%6,%7}, {%8,%9}, {%0,%1,%2,%3};\n"
        : "+f"(c[0]), "+f"(c[1]), "+f"(c[2]), "+f"(c[3])
        : "r"(a[0]), "r"(a[1]), "r"(a[2]), "r"(a[3]), "r"(b0), "r"(b1));
}

__device__ __forceinline__ void gemm_f16s(
    const __half* __restrict__ Ah, const __half* __restrict__ Al,
    const __half* __restrict__ Bh,
    float* __restrict__ C, int N, int K)
{
    __shared__ __half sm[3 * 128 * SRW];   // 30720 bytes
    __half* sAh = sm;
    __half* sAl = sm + 128 * SRW;
    __half* sBh = sm + 2 * 128 * SRW;

    int tid  = threadIdx.x;
    int bm   = blockIdx.y * 128;
    int bn   = blockIdx.x * 128;
    int warp = tid >> 5, lane = tid & 31;
    int wm   = (warp & 1) * 64;
    int wn   = (warp >> 1) * 32;
    int g    = lane >> 2, tg = lane & 3;

    float acc[4][4][4];
#pragma unroll
    for (int i = 0; i < 4; ++i)
#pragma unroll
        for (int j = 0; j < 4; ++j)
#pragma unroll
            for (int v = 0; v < 4; ++v) acc[i][j][v] = 0.f;

    int row  = tid >> 1;             // 0..127
    int half = (tid & 1) * 16;       // fp16 offset within 32-wide tile row
    const __half* gAh = Ah + (size_t)(bm + row) * K + half;
    const __half* gAl = Al + (size_t)(bm + row) * K + half;
    const __half* gBh = Bh + (size_t)(bn + row) * K + half;
    int sidx = row * SRW + half;

    // preload chunk 0 into regs
    uint4 pa0 = *(const uint4*)(gAh);
    uint4 pa1 = *(const uint4*)(gAh + 8);
    uint4 pl0 = *(const uint4*)(gAl);
    uint4 pl1 = *(const uint4*)(gAl + 8);
    uint4 pb0 = *(const uint4*)(gBh);
    uint4 pb1 = *(const uint4*)(gBh + 8);

    int nt = K / 32;                 // 24
    for (int t = 0; t < nt; ++t) {
        __syncthreads();             // consumers of previous tile done
        *(uint4*)(sAh + sidx)     = pa0;  *(uint4*)(sAh + sidx + 8) = pa1;
        *(uint4*)(sAl + sidx)     = pl0;  *(uint4*)(sAl + sidx + 8) = pl1;
        *(uint4*)(sBh + sidx)     = pb0;  *(uint4*)(sBh + sidx + 8) = pb1;
        __syncthreads();             // tile published

        if (t + 1 < nt) {            // issue next chunk's loads; overlap MMAs
            int k0 = (t + 1) * 32;
            pa0 = *(const uint4*)(gAh + k0);
            pa1 = *(const uint4*)(gAh + k0 + 8);
            pl0 = *(const uint4*)(gAl + k0);
            pl1 = *(const uint4*)(gAl + k0 + 8);
            pb0 = *(const uint4*)(gBh + k0);
            pb1 = *(const uint4*)(gBh + k0 + 8);
        }

#pragma unroll
        for (int ks = 0; ks < 2; ++ks) {
            int kk = ks * 16 + 2 * tg;
            uint32_t ah[4][4], al[4][4];
#pragma unroll
            for (int i = 0; i < 4; ++i) {
                int r0 = wm + i * 16 + g;
                ah[i][0] = *(const uint32_t*)&sAh[ r0      * SRW + kk];
                ah[i][1] = *(const uint32_t*)&sAh[(r0 + 8) * SRW + kk];
                ah[i][2] = *(const uint32_t*)&sAh[ r0      * SRW + kk + 8];
                ah[i][3] = *(const uint32_t*)&sAh[(r0 + 8) * SRW + kk + 8];
                al[i][0] = *(const uint32_t*)&sAl[ r0      * SRW + kk];
                al[i][1] = *(const uint32_t*)&sAl[(r0 + 8) * SRW + kk];
                al[i][2] = *(const uint32_t*)&sAl[ r0      * SRW + kk + 8];
                al[i][3] = *(const uint32_t*)&sAl[(r0 + 8) * SRW + kk + 8];
            }
#pragma unroll
            for (int j = 0; j < 4; ++j) {
                int n0 = wn + j * 8 + g;
                uint32_t bh0 = *(const uint32_t*)&sBh[n0 * SRW + kk];
                uint32_t bh1 = *(const uint32_t*)&sBh[n0 * SRW + kk + 8];
#pragma unroll
                for (int i = 0; i < 4; ++i) {
                    mma_f16(acc[i][j], ah[i], bh0, bh1);   // hi * B
                    mma_f16(acc[i][j], al[i], bh0, bh1);   // lo * B
                }
            }
        }
    }

#pragma unroll
    for (int i = 0; i < 4; ++i) {
        int r0 = bm + wm + i * 16 + g;
#pragma unroll
        for (int j = 0; j < 4; ++j) {
            int col = bn + wn + j * 8 + tg * 2;
            *(float2*)(C + (size_t)r0      * N + col) = make_float2(acc[i][j][0], acc[i][j][1]);
            *(float2*)(C + (size_t)(r0+8)  * N + col) = make_float2(acc[i][j][2], acc[i][j][3]);
        }
    }
}

// wrappers bind device globals IN DEVICE CODE (proven pattern)
__global__ __launch_bounds__(256) void gemm1_kernel() {
    gemm_f16s(g_xh, g_xl, g_wih, g_u, N1, KD);
}
__global__ __launch_bounds__(256) void gemm2_kernel(float* __restrict__ out) {
    gemm_f16s(g_yh, g_yl, g_woh, out, KD, KD);
}

// ---------------- Phase A: per-chunk local scan from zero state ----------------
__global__ void scanA_kernel() {
    int d = blockIdx.x * 256 + threadIdx.x;
    int j = blockIdx.y, b = blockIdx.z;
    int ch0 = d * RANK;
    float2 a[RANK], bb[RANK], cc[RANK], s[RANK];
#pragma unroll
    for (int r = 0; r < RANK; ++r) {
        a[r] = g_ca[ch0 + r]; bb[r] = g_cb[ch0 + r]; cc[r] = g_cc[ch0 + r];
        s[r] = make_float2(0.f, 0.f);
    }
    int t0 = j * CL;
    const float4* up = (const float4*)(g_u + (size_t)(b * TLEN + t0) * N1 + d * (RANK * 2));
    float* yp = g_y + (size_t)(b * TLEN + t0) * D_MODEL + d;
    for (int t = 0; t < CL; ++t) {
        float4 u0 = up[0], u1 = up[1];
        float ur[4] = {u0.x, u0.z, u1.x, u1.z};
        float ui[4] = {u0.y, u0.w, u1.y, u1.w};
        float y = 0.f;
#pragma unroll
        for (int r = 0; r < RANK; ++r) {
            float bur = bb[r].x * ur[r] - bb[r].y * ui[r];
            float bui = bb[r].x * ui[r] + bb[r].y * ur[r];
            float sr  = a[r].x * s[r].x - a[r].y * s[r].y + bur;
            float si  = a[r].x * s[r].y + a[r].y * s[r].x + bui;
            s[r] = make_float2(sr, si);
            y += cc[r].x * sr - cc[r].y * si;
        }
        *yp = y;
        up += N1 / 4;
        yp += D_MODEL;
    }
    float2* sp = g_Sloc + (size_t)(b * NCHUNK + j) * NCH + ch0;
#pragma unroll
    for (int r = 0; r < RANK; ++r) sp[r] = s[r];
}

// ---------------- Phase B: sequential carry combine across chunks ----------------
__global__ void scanB_kernel() {
    int idx = blockIdx.x * 256 + threadIdx.x;
    if (idx >= BATCH * NCH) return;
    int b = idx / NCH, ch = idx % NCH;
    float2 aL = g_aL[ch];
    float2 carry = make_float2(0.f, 0.f);
    for (int j = 0; j < NCHUNK; ++j) {
        g_carry[(size_t)(b * NCHUNK + j) * NCH + ch] = carry;
        float2 S = g_Sloc[(size_t)(b * NCHUNK + j) * NCH + ch];
        carry = make_float2(aL.x * carry.x - aL.y * carry.y + S.x,
                            aL.x * carry.y + aL.y * carry.x + S.y);
    }
}

// ---------------- Phase C: y += Re(c * a^p * carry) ----------------
__global__ void scanC_kernel() {
    int d = blockIdx.x * 256 + threadIdx.x;
    int j = blockIdx.y + 1, b = blockIdx.z;
    int ch0 = d * RANK;
    float2 a[RANK], w[RANK];
#pragma unroll
    for (int r = 0; r < RANK; ++r) {
        a[r] = g_ca[ch0 + r];
        float2 carry = g_carry[(size_t)(b * NCHUNK + j) * NCH + ch0 + r];
        float2 c = g_cc[ch0 + r];
        w[r] = make_float2(c.x * carry.x - c.y * carry.y,
                           c.x * carry.y + c.y * carry.x);
    }
    int t0 = j * CL;
    float* yp = g_y + (size_t)(b * TLEN + t0) * D_MODEL + d;
    for (int t = 0; t < CL; ++t) {
        float corr = 0.f;
#pragma unroll
        for (int r = 0; r < RANK; ++r) {
            w[r] = make_float2(w[r].x * a[r].x - w[r].y * a[r].y,
                               w[r].x * a[r].y + w[r].y * a[r].x);
            corr += w[r].x;
        }
        *yp += corr;
        yp += D_MODEL;
    }
}

// ---------------- launch (no device symbols passed from host) ----------------
extern "C" void kernel_launch(void* const* d_in, const int* in_sizes, int n_in,
                              void* d_out, int out_size) {
    const float* x    = (const float*)d_in[0];
    const float* nw   = (const float*)d_in[1];
    const float* Win  = (const float*)d_in[2];
    const float* Wout = (const float*)d_in[3];
    const float* ap   = (const float*)d_in[4];
    const float* bp   = (const float*)d_in[5];
    const float* cp   = (const float*)d_in[6];
    float* out = (float*)d_out;

    coef_kernel<<<(NCH + 255) / 256, 256>>>(ap, bp, cp);
    round_win_kernel<<<(N1 * KD + 255) / 256, 256>>>(Win);
    round_wout_kernel<<<(KD * KD + 255) / 256, 256>>>(Wout);
    rmsnorm_kernel<<<MROWS, 256>>>(x, nw);
    gemm1_kernel<<<dim3(N1 / 128, MROWS / 128), 256>>>();
    scanA_kernel<<<dim3(D_MODEL / 256, NCHUNK, BATCH), 256>>>();
    scanB_kernel<<<(BATCH * NCH + 255) / 256, 256>>>();
    scanC_kernel<<<dim3(D_MODEL / 256, NCHUNK - 1, BATCH), 256>>>();
    split_y_kernel<<<(MROWS * KD + 255) / 256, 256>>>();
    gemm2_kernel<<<dim3(KD / 128, MROWS / 128), 256>>>(out);
}

// round 10
// speedup vs baseline: 3.2078x; 1.3687x over previous
#include <cuda_runtime.h>
#include <cuda_fp16.h>
#include <math.h>
#include <stdint.h>

#define D_MODEL 768
#define RANK 4
#define BATCH 2
#define TLEN 2048
#define MROWS (BATCH*TLEN)          // 4096
#define N1 (D_MODEL*RANK*2)         // 6144
#define KD D_MODEL                  // 768
#define NCH (D_MODEL*RANK)          // 3072
#define NCHUNK 128
#define CL (TLEN/NCHUNK)            // 16

// ---------------- scratch (static __device__, no allocations) ----------------
__device__ __half g_xh [MROWS*KD];                    // x rounded fp16
__device__ __half g_wih[N1*KD];                       // W_in  rounded fp16
__device__ __half g_woh[KD*KD];                       // W_out rounded fp16
__device__ __half g_yh [MROWS*KD], g_yl [MROWS*KD];   // y split hi/lo (gemm2 stays 2-term)
__device__ float  g_u[MROWS*N1];
__device__ float  g_y[MROWS*KD];
__device__ float2 g_ca[NCH], g_cb[NCH], g_cc[NCH], g_aL[NCH];
__device__ float2 g_Sloc [BATCH*NCHUNK*NCH];
__device__ float2 g_carry[BATCH*NCHUNK*NCH];

// ---------------- coefficient precompute ----------------
__global__ void coef_kernel(const float* __restrict__ ap,
                            const float* __restrict__ bp,
                            const float* __restrict__ cp) {
    int i = blockIdx.x * blockDim.x + threadIdx.x;
    if (i >= NCH) return;
    float2 a = make_float2(tanhf(ap[2*i]) * 0.97f, tanhf(ap[2*i+1]) * 0.97f);
    float2 b = make_float2(tanhf(bp[2*i]),         tanhf(bp[2*i+1]));
    float2 c = make_float2(tanhf(cp[2*i]),         tanhf(cp[2*i+1]));
    g_ca[i] = a; g_cb[i] = b; g_cc[i] = c;
    float2 p = a;
    for (int k = 1; k < CL; ++k)
        p = make_float2(p.x*a.x - p.y*a.y, p.x*a.y + p.y*a.x);
    g_aL[i] = p;
}

// ---------------- fp16 rounding / splitting ----------------
__device__ __forceinline__ void split1(float v, __half& h, __half& l) {
    h = __float2half(v);
    l = __float2half(v - __half2float(h));
}
__global__ void round_win_kernel(const float* __restrict__ w) {
    int i = blockIdx.x * 256 + threadIdx.x;
    if (i < N1*KD) g_wih[i] = __float2half(w[i]);
}
__global__ void round_wout_kernel(const float* __restrict__ w) {
    int i = blockIdx.x * 256 + threadIdx.x;
    if (i < KD*KD) g_woh[i] = __float2half(w[i]);
}
__global__ void split_y_kernel() {
    int i = blockIdx.x * 256 + threadIdx.x;
    if (i < MROWS*KD) split1(g_y[i], g_yh[i], g_yl[i]);
}

// ---------------- RMSNorm -> fp16 ----------------
__global__ void rmsnorm_kernel(const float* __restrict__ x,
                               const float* __restrict__ w) {
    int row = blockIdx.x;
    const float* xr = x + (size_t)row * KD;
    float s = 0.f;
    for (int k = threadIdx.x; k < KD; k += 256) { float v = xr[k]; s += v * v; }
    __shared__ float red[256];
    red[threadIdx.x] = s; __syncthreads();
    for (int off = 128; off > 0; off >>= 1) {
        if (threadIdx.x < off) red[threadIdx.x] += red[threadIdx.x + off];
        __syncthreads();
    }
    float scale = rsqrtf(red[0] * (1.0f / KD) + 1e-6f);
    for (int k = threadIdx.x; k < KD; k += 256)
        g_xh[(size_t)row*KD + k] = __float2half(xr[k] * scale * w[k]);
}

// ============================================================================
// fp16 GEMMs, fp32 accum, mma.m16n8k16.  BM=BN=128, BK=32, 256 threads,
// warp grid 2x4, warp tile 64x32, register-prefetch pipelined smem.
// Fragment indexing identical to the R5/R7-proven kernels.
// gemm_f16_1: C = Ah * Bh^T                (1 MMA/step — gemm1, hot path)
// gemm_f16_2: C = (Ah+Al) * Bh^T           (2 MMA/step — gemm2, precision)
// ============================================================================
#define SRW 40   // smem row stride in fp16 (80B)

__device__ __forceinline__ void mma_f16(float* c, const uint32_t* a,
                                        uint32_t b0, uint32_t b1) {
    asm volatile(
        "mma.sync.aligned.m16n8k16.row.col.f32.f16.f16.f32 "
        "{%0,%1,%2,%3}, {%4,%5,%6,%7}, {%8,%9}, {%0,%1,%2,%3};\n"
        : "+f"(c[0]), "+f"(c[1]), "+f"(c[2]), "+f"(c[3])
        : "r"(a[0]), "r"(a[1]), "r"(a[2]), "r"(a[3]), "r"(b0), "r"(b1));
}

__device__ __forceinline__ void gemm_f16_1(
    const __half* __restrict__ Ah, const __half* __restrict__ Bh,
    float* __restrict__ C, int N, int K)
{
    __shared__ __half sm[2 * 128 * SRW];   // 20480 bytes
    __half* sAh = sm;
    __half* sBh = sm + 128 * SRW;

    int tid  = threadIdx.x;
    int bm   = blockIdx.y * 128;
    int bn   = blockIdx.x * 128;
    int warp = tid >> 5, lane = tid & 31;
    int wm   = (warp & 1) * 64;
    int wn   = (warp >> 1) * 32;
    int g    = lane >> 2, tg = lane & 3;

    float acc[4][4][4];
#pragma unroll
    for (int i = 0; i < 4; ++i)
#pragma unroll
        for (int j = 0; j < 4; ++j)
#pragma unroll
            for (int v = 0; v < 4; ++v) acc[i][j][v] = 0.f;

    int row  = tid >> 1;
    int half = (tid & 1) * 16;
    const __half* gAh = Ah + (size_t)(bm + row) * K + half;
    const __half* gBh = Bh + (size_t)(bn + row) * K + half;
    int sidx = row * SRW + half;

    uint4 pa0 = *(const uint4*)(gAh);
    uint4 pa1 = *(const uint4*)(gAh + 8);
    uint4 pb0 = *(const uint4*)(gBh);
    uint4 pb1 = *(const uint4*)(gBh + 8);

    int nt = K / 32;                 // 24
    for (int t = 0; t < nt; ++t) {
        __syncthreads();
        *(uint4*)(sAh + sidx)     = pa0;  *(uint4*)(sAh + sidx + 8) = pa1;
        *(uint4*)(sBh + sidx)     = pb0;  *(uint4*)(sBh + sidx + 8) = pb1;
        __syncthreads();

        if (t + 1 < nt) {
            int k0 = (t + 1) * 32;
            pa0 = *(const uint4*)(gAh + k0);
            pa1 = *(const uint4*)(gAh + k0 + 8);
            pb0 = *(const uint4*)(gBh + k0);
            pb1 = *(const uint4*)(gBh + k0 + 8);
        }

#pragma unroll
        for (int ks = 0; ks < 2; ++ks) {
            int kk = ks * 16 + 2 * tg;
            uint32_t ah[4][4];
#pragma unroll
            for (int i = 0; i < 4; ++i) {
                int r0 = wm + i * 16 + g;
                ah[i][0] = *(const uint32_t*)&sAh[ r0      * SRW + kk];
                ah[i][1] = *(const uint32_t*)&sAh[(r0 + 8) * SRW + kk];
                ah[i][2] = *(const uint32_t*)&sAh[ r0      * SRW + kk + 8];
                ah[i][3] = *(const uint32_t*)&sAh[(r0 + 8) * SRW + kk + 8];
            }
#pragma unroll
            for (int j = 0; j < 4; ++j) {
                int n0 = wn + j * 8 + g;
                uint32_t bh0 = *(const uint32_t*)&sBh[n0 * SRW + kk];
                uint32_t bh1 = *(const uint32_t*)&sBh[n0 * SRW + kk + 8];
#pragma unroll
                for (int i = 0; i < 4; ++i)
                    mma_f16(acc[i][j], ah[i], bh0, bh1);
            }
        }
    }

#pragma unroll
    for (int i = 0; i < 4; ++i) {
        int r0 = bm + wm + i * 16 + g;
#pragma unroll
        for (int j = 0; j < 4; ++j) {
            int col = bn + wn + j * 8 + tg * 2;
            *(float2*)(C + (size_t)r0      * N + col) = make_float2(acc[i][j][0], acc[i][j][1]);
            *(float2*)(C + (size_t)(r0+8)  * N + col) = make_float2(acc[i][j][2], acc[i][j][3]);
        }
    }
}

__device__ __forceinline__ void gemm_f16_2(
    const __half* __restrict__ Ah, const __half* __restrict__ Al,
    const __half* __restrict__ Bh,
    float* __restrict__ C, int N, int K)
{
    __shared__ __half sm[3 * 128 * SRW];   // 30720 bytes
    __half* sAh = sm;
    __half* sAl = sm + 128 * SRW;
    __half* sBh = sm + 2 * 128 * SRW;

    int tid  = threadIdx.x;
    int bm   = blockIdx.y * 128;
    int bn   = blockIdx.x * 128;
    int warp = tid >> 5, lane = tid & 31;
    int wm   = (warp & 1) * 64;
    int wn   = (warp >> 1) * 32;
    int g    = lane >> 2, tg = lane & 3;

    float acc[4][4][4];
#pragma unroll
    for (int i = 0; i < 4; ++i)
#pragma unroll
        for (int j = 0; j < 4; ++j)
#pragma unroll
            for (int v = 0; v < 4; ++v) acc[i][j][v] = 0.f;

    int row  = tid >> 1;
    int half = (tid & 1) * 16;
    const __half* gAh = Ah + (size_t)(bm + row) * K + half;
    const __half* gAl = Al + (size_t)(bm + row) * K + half;
    const __half* gBh = Bh + (size_t)(bn + row) * K + half;
    int sidx = row * SRW + half;

    uint4 pa0 = *(const uint4*)(gAh);
    uint4 pa1 = *(const uint4*)(gAh + 8);
    uint4 pl0 = *(const uint4*)(gAl);
    uint4 pl1 = *(const uint4*)(gAl + 8);
    uint4 pb0 = *(const uint4*)(gBh);
    uint4 pb1 = *(const uint4*)(gBh + 8);

    int nt = K / 32;
    for (int t = 0; t < nt; ++t) {
        __syncthreads();
        *(uint4*)(sAh + sidx)     = pa0;  *(uint4*)(sAh + sidx + 8) = pa1;
        *(uint4*)(sAl + sidx)     = pl0;  *(uint4*)(sAl + sidx + 8) = pl1;
        *(uint4*)(sBh + sidx)     = pb0;  *(uint4*)(sBh + sidx + 8) = pb1;
        __syncthreads();

        if (t + 1 < nt) {
            int k0 = (t + 1) * 32;
            pa0 = *(const uint4*)(gAh + k0);
            pa1 = *(const uint4*)(gAh + k0 + 8);
            pl0 = *(const uint4*)(gAl + k0);
            pl1 = *(const uint4*)(gAl + k0 + 8);
            pb0 = *(const uint4*)(gBh + k0);
            pb1 = *(const uint4*)(gBh + k0 + 8);
        }

#pragma unroll
        for (int ks = 0; ks < 2; ++ks) {
            int kk = ks * 16 + 2 * tg;
            uint32_t ah[4][4], al[4][4];
#pragma unroll
            for (int i = 0; i < 4; ++i) {
                int r0 = wm + i * 16 + g;
                ah[i][0] = *(const uint32_t*)&sAh[ r0      * SRW + kk];
                ah[i][1] = *(const uint32_t*)&sAh[(r0 + 8) * SRW + kk];
                ah[i][2] = *(const uint32_t*)&sAh[ r0      * SRW + kk + 8];
                ah[i][3] = *(const uint32_t*)&sAh[(r0 + 8) * SRW + kk + 8];
                al[i][0] = *(const uint32_t*)&sAl[ r0      * SRW + kk];
                al[i][1] = *(const uint32_t*)&sAl[(r0 + 8) * SRW + kk];
                al[i][2] = *(const uint32_t*)&sAl[ r0      * SRW + kk + 8];
                al[i][3] = *(const uint32_t*)&sAl[(r0 + 8) * SRW + kk + 8];
            }
#pragma unroll
            for (int j = 0; j < 4; ++j) {
                int n0 = wn + j * 8 + g;
                uint32_t bh0 = *(const uint32_t*)&sBh[n0 * SRW + kk];
                uint32_t bh1 = *(const uint32_t*)&sBh[n0 * SRW + kk + 8];
#pragma unroll
                for (int i = 0; i < 4; ++i) {
                    mma_f16(acc[i][j], ah[i], bh0, bh1);
                    mma_f16(acc[i][j], al[i], bh0, bh1);
                }
            }
        }
    }

#pragma unroll
    for (int i = 0; i < 4; ++i) {
        int r0 = bm + wm + i * 16 + g;
#pragma unroll
        for (int j = 0; j < 4; ++j) {
            int col = bn + wn + j * 8 + tg * 2;
            *(float2*)(C + (size_t)r0      * N + col) = make_float2(acc[i][j][0], acc[i][j][1]);
            *(float2*)(C + (size_t)(r0+8)  * N + col) = make_float2(acc[i][j][2], acc[i][j][3]);
        }
    }
}

// wrappers bind device globals IN DEVICE CODE (proven pattern)
__global__ __launch_bounds__(256) void gemm1_kernel() {
    gemm_f16_1(g_xh, g_wih, g_u, N1, KD);
}
__global__ __launch_bounds__(256) void gemm2_kernel(float* __restrict__ out) {
    gemm_f16_2(g_yh, g_yl, g_woh, out, KD, KD);
}

// ---------------- Phase A: per-chunk local scan from zero state ----------------
__global__ void scanA_kernel() {
    int d = blockIdx.x * 256 + threadIdx.x;
    int j = blockIdx.y, b = blockIdx.z;
    int ch0 = d * RANK;
    float2 a[RANK], bb[RANK], cc[RANK], s[RANK];
#pragma unroll
    for (int r = 0; r < RANK; ++r) {
        a[r] = g_ca[ch0 + r]; bb[r] = g_cb[ch0 + r]; cc[r] = g_cc[ch0 + r];
        s[r] = make_float2(0.f, 0.f);
    }
    int t0 = j * CL;
    const float4* up = (const float4*)(g_u + (size_t)(b * TLEN + t0) * N1 + d * (RANK * 2));
    float* yp = g_y + (size_t)(b * TLEN + t0) * D_MODEL + d;
    for (int t = 0; t < CL; ++t) {
        float4 u0 = up[0], u1 = up[1];
        float ur[4] = {u0.x, u0.z, u1.x, u1.z};
        float ui[4] = {u0.y, u0.w, u1.y, u1.w};
        float y = 0.f;
#pragma unroll
        for (int r = 0; r < RANK; ++r) {
            float bur = bb[r].x * ur[r] - bb[r].y * ui[r];
            float bui = bb[r].x * ui[r] + bb[r].y * ur[r];
            float sr  = a[r].x * s[r].x - a[r].y * s[r].y + bur;
            float si  = a[r].x * s[r].y + a[r].y * s[r].x + bui;
            s[r] = make_float2(sr, si);
            y += cc[r].x * sr - cc[r].y * si;
        }
        *yp = y;
        up += N1 / 4;
        yp += D_MODEL;
    }
    float2* sp = g_Sloc + (size_t)(b * NCHUNK + j) * NCH + ch0;
#pragma unroll
    for (int r = 0; r < RANK; ++r) sp[r] = s[r];
}

// ---------------- Phase B: sequential carry combine across chunks ----------------
__global__ void scanB_kernel() {
    int idx = blockIdx.x * 256 + threadIdx.x;
    if (idx >= BATCH * NCH) return;
    int b = idx / NCH, ch = idx % NCH;
    float2 aL = g_aL[ch];
    float2 carry = make_float2(0.f, 0.f);
    for (int j = 0; j < NCHUNK; ++j) {
        g_carry[(size_t)(b * NCHUNK + j) * NCH + ch] = carry;
        float2 S = g_Sloc[(size_t)(b * NCHUNK + j) * NCH + ch];
        carry = make_float2(aL.x * carry.x - aL.y * carry.y + S.x,
                            aL.x * carry.y + aL.y * carry.x + S.y);
    }
}

// ---------------- Phase C: y += Re(c * a^p * carry) ----------------
__global__ void scanC_kernel() {
    int d = blockIdx.x * 256 + threadIdx.x;
    int j = blockIdx.y + 1, b = blockIdx.z;
    int ch0 = d * RANK;
    float2 a[RANK], w[RANK];
#pragma unroll
    for (int r = 0; r < RANK; ++r) {
        a[r] = g_ca[ch0 + r];
        float2 carry = g_carry[(size_t)(b * NCHUNK + j) * NCH + ch0 + r];
        float2 c = g_cc[ch0 + r];
        w[r] = make_float2(c.x * carry.x - c.y * carry.y,
                           c.x * carry.y + c.y * carry.x);
    }
    int t0 = j * CL;
    float* yp = g_y + (size_t)(b * TLEN + t0) * D_MODEL + d;
    for (int t = 0; t < CL; ++t) {
        float corr = 0.f;
#pragma unroll
        for (int r = 0; r < RANK; ++r) {
            w[r] = make_float2(w[r].x * a[r].x - w[r].y * a[r].y,
                               w[r].x * a[r].y + w[r].y * a[r].x);
            corr += w[r].x;
        }
        *yp += corr;
        yp += D_MODEL;
    }
}

// ---------------- launch (no device symbols passed from host) ----------------
extern "C" void kernel_launch(void* const* d_in, const int* in_sizes, int n_in,
                              void* d_out, int out_size) {
    const float* x    = (const float*)d_in[0];
    const float* nw   = (const float*)d_in[1];
    const float* Win  = (const float*)d_in[2];
    const float* Wout = (const float*)d_in[3];
    const float* ap   = (const float*)d_in[4];
    const float* bp   = (const float*)d_in[5];
    const float* cp   = (const float*)d_in[6];
    float* out = (float*)d_out;

    coef_kernel<<<(NCH + 255) / 256, 256>>>(ap, bp, cp);
    round_win_kernel<<<(N1 * KD + 255) / 256, 256>>>(Win);
    round_wout_kernel<<<(KD * KD + 255) / 256, 256>>>(Wout);
    rmsnorm_kernel<<<MROWS, 256>>>(x, nw);
    gemm1_kernel<<<dim3(N1 / 128, MROWS / 128), 256>>>();
    scanA_kernel<<<dim3(D_MODEL / 256, NCHUNK, BATCH), 256>>>();
    scanB_kernel<<<(BATCH * NCH + 255) / 256, 256>>>();
    scanC_kernel<<<dim3(D_MODEL / 256, NCHUNK - 1, BATCH), 256>>>();
    split_y_kernel<<<(MROWS * KD + 255) / 256, 256>>>();
    gemm2_kernel<<<dim3(KD / 128, MROWS / 128), 256>>>(out);
}

// round 11
// speedup vs baseline: 3.4297x; 1.0692x over previous
#include <cuda_runtime.h>
#include <cuda_fp16.h>
#include <math.h>
#include <stdint.h>

#define D_MODEL 768
#define RANK 4
#define BATCH 2
#define TLEN 2048
#define MROWS (BATCH*TLEN)          // 4096
#define N1 (D_MODEL*RANK*2)         // 6144
#define KD D_MODEL                  // 768
#define NCH (D_MODEL*RANK)          // 3072
#define NCHUNK 128
#define CL (TLEN/NCHUNK)            // 16

// ---------------- scratch (static __device__, no allocations) ----------------
__device__ __half g_xh [MROWS*KD];                    // x rounded fp16
__device__ __half g_wih[N1*KD];                       // W_in  rounded fp16
__device__ __half g_woh[KD*KD];                       // W_out rounded fp16
__device__ __half g_yh [MROWS*KD], g_yl [MROWS*KD];   // y split hi/lo
__device__ float  g_u[MROWS*N1];
__device__ float  g_y[MROWS*KD];
__device__ float2 g_ca[NCH], g_cb[NCH], g_cc[NCH], g_aL[NCH];
__device__ float2 g_Sloc [BATCH*NCHUNK*NCH];
__device__ float2 g_carry[BATCH*NCHUNK*NCH];

// ---------------- coefficient precompute ----------------
__global__ void coef_kernel(const float* __restrict__ ap,
                            const float* __restrict__ bp,
                            const float* __restrict__ cp) {
    int i = blockIdx.x * blockDim.x + threadIdx.x;
    if (i >= NCH) return;
    float2 a = make_float2(tanhf(ap[2*i]) * 0.97f, tanhf(ap[2*i+1]) * 0.97f);
    float2 b = make_float2(tanhf(bp[2*i]),         tanhf(bp[2*i+1]));
    float2 c = make_float2(tanhf(cp[2*i]),         tanhf(cp[2*i+1]));
    g_ca[i] = a; g_cb[i] = b; g_cc[i] = c;
    float2 p = a;
    for (int k = 1; k < CL; ++k)
        p = make_float2(p.x*a.x - p.y*a.y, p.x*a.y + p.y*a.x);
    g_aL[i] = p;
}

// ---------------- fp16 rounding / splitting ----------------
__device__ __forceinline__ void split1(float v, __half& h, __half& l) {
    h = __float2half(v);
    l = __float2half(v - __half2float(h));
}
__global__ void round_win_kernel(const float* __restrict__ w) {
    int i = blockIdx.x * 256 + threadIdx.x;
    if (i < N1*KD) g_wih[i] = __float2half(w[i]);
}
__global__ void round_wout_kernel(const float* __restrict__ w) {
    int i = blockIdx.x * 256 + threadIdx.x;
    if (i < KD*KD) g_woh[i] = __float2half(w[i]);
}
__global__ void split_y_kernel() {
    int i = blockIdx.x * 256 + threadIdx.x;
    if (i < MROWS*KD) split1(g_y[i], g_yh[i], g_yl[i]);
}

// ---------------- RMSNorm -> fp16 ----------------
__global__ void rmsnorm_kernel(const float* __restrict__ x,
                               const float* __restrict__ w) {
    int row = blockIdx.x;
    const float* xr = x + (size_t)row * KD;
    float s = 0.f;
    for (int k = threadIdx.x; k < KD; k += 256) { float v = xr[k]; s += v * v; }
    __shared__ float red[256];
    red[threadIdx.x] = s; __syncthreads();
    for (int off = 128; off > 0; off >>= 1) {
        if (threadIdx.x < off) red[threadIdx.x] += red[threadIdx.x + off];
        __syncthreads();
    }
    float scale = rsqrtf(red[0] * (1.0f / KD) + 1e-6f);
    for (int k = threadIdx.x; k < KD; k += 256)
        g_xh[(size_t)row*KD + k] = __float2half(xr[k] * scale * w[k]);
}

// ============================================================================
// fp16 GEMMs, fp32 accum, mma.m16n8k16.  BM=BN=128, BK=32, 256 threads,
// warp grid 2x4, warp tile 64x32.  Fragment indexing proven in R5/R7/R8.
// gemm1: 1-term, cp.async double-buffered, __launch_bounds__(256,2).
// gemm2: 2-term register-prefetch (unchanged proven code).
// ============================================================================
#define SRW 40                       // smem row stride in fp16 (80B)
#define SSTG (2 * 128 * SRW)         // halves per stage (A tile + B tile)

__device__ __forceinline__ void mma_f16(float* c, const uint32_t* a,
                                        uint32_t b0, uint32_t b1) {
    asm volatile(
        "mma.sync.aligned.m16n8k16.row.col.f32.f16.f16.f32 "
        "{%0,%1,%2,%3}, {%4,%5,%6,%7}, {%8,%9}, {%0,%1,%2,%3};\n"
        : "+f"(c[0]), "+f"(c[1]), "+f"(c[2]), "+f"(c[3])
        : "r"(a[0]), "r"(a[1]), "r"(a[2]), "r"(a[3]), "r"(b0), "r"(b1));
}
__device__ __forceinline__ void cpa16(uint32_t s, const void* g) {
    asm volatile("cp.async.cg.shared.global [%0], [%1], 16;\n" :: "r"(s), "l"(g));
}

__global__ __launch_bounds__(256, 2) void gemm1_kernel() {
    const __half* __restrict__ Ah = g_xh;
    const __half* __restrict__ Bh = g_wih;
    float* __restrict__ C = g_u;
    const int N = N1, K = KD;

    __shared__ __half sm[2 * SSTG];    // 40960 bytes (2 stages)

    int tid  = threadIdx.x;
    int bm   = blockIdx.y * 128;
    int bn   = blockIdx.x * 128;
    int warp = tid >> 5, lane = tid & 31;
    int wm   = (warp & 1) * 64;
    int wn   = (warp >> 1) * 32;
    int g    = lane >> 2, tg = lane & 3;

    float acc[4][4][4];
#pragma unroll
    for (int i = 0; i < 4; ++i)
#pragma unroll
        for (int j = 0; j < 4; ++j)
#pragma unroll
            for (int v = 0; v < 4; ++v) acc[i][j][v] = 0.f;

    int row  = tid >> 1;
    int half = (tid & 1) * 16;
    const __half* gA = Ah + (size_t)(bm + row) * K + half;
    const __half* gB = Bh + (size_t)(bn + row) * K + half;
    uint32_t sA = (uint32_t)__cvta_generic_to_shared(sm) + (uint32_t)(row * SRW + half) * 2u;
    uint32_t sB = sA + 128u * SRW * 2u;

    const int nt = K / 32;             // 24
    // prologue: stages 0 and 1
#pragma unroll
    for (int st = 0; st < 2; ++st) {
        uint32_t off = (uint32_t)st * SSTG * 2u;
        int k0 = st * 32;
        cpa16(sA + off,      gA + k0);
        cpa16(sA + off + 16, gA + k0 + 8);
        cpa16(sB + off,      gB + k0);
        cpa16(sB + off + 16, gB + k0 + 8);
        asm volatile("cp.async.commit_group;\n");
    }

    for (int t = 0; t < nt; ++t) {
        if (t + 1 < nt) asm volatile("cp.async.wait_group 1;\n");
        else            asm volatile("cp.async.wait_group 0;\n");
        __syncthreads();                              // stage t resident for all

        const __half* As = sm + (t & 1) * SSTG;
        const __half* Bs = As + 128 * SRW;
#pragma unroll
        for (int ks = 0; ks < 2; ++ks) {
            int kk = ks * 16 + 2 * tg;
            uint32_t ah[4][4];
#pragma unroll
            for (int i = 0; i < 4; ++i) {
                int r0 = wm + i * 16 + g;
                ah[i][0] = *(const uint32_t*)&As[ r0      * SRW + kk];
                ah[i][1] = *(const uint32_t*)&As[(r0 + 8) * SRW + kk];
                ah[i][2] = *(const uint32_t*)&As[ r0      * SRW + kk + 8];
                ah[i][3] = *(const uint32_t*)&As[(r0 + 8) * SRW + kk + 8];
            }
#pragma unroll
            for (int j = 0; j < 4; ++j) {
                int n0 = wn + j * 8 + g;
                uint32_t bh0 = *(const uint32_t*)&Bs[n0 * SRW + kk];
                uint32_t bh1 = *(const uint32_t*)&Bs[n0 * SRW + kk + 8];
#pragma unroll
                for (int i = 0; i < 4; ++i)
                    mma_f16(acc[i][j], ah[i], bh0, bh1);
            }
        }
        __syncthreads();                              // all warps done with stage t
        if (t + 2 < nt) {
            uint32_t off = (uint32_t)(t & 1) * SSTG * 2u;
            int k0 = (t + 2) * 32;
            cpa16(sA + off,      gA + k0);
            cpa16(sA + off + 16, gA + k0 + 8);
            cpa16(sB + off,      gB + k0);
            cpa16(sB + off + 16, gB + k0 + 8);
            asm volatile("cp.async.commit_group;\n");
        }
    }

#pragma unroll
    for (int i = 0; i < 4; ++i) {
        int r0 = bm + wm + i * 16 + g;
#pragma unroll
        for (int j = 0; j < 4; ++j) {
            int col = bn + wn + j * 8 + tg * 2;
            *(float2*)(C + (size_t)r0      * N + col) = make_float2(acc[i][j][0], acc[i][j][1]);
            *(float2*)(C + (size_t)(r0+8)  * N + col) = make_float2(acc[i][j][2], acc[i][j][3]);
        }
    }
}

// ---- gemm2: 2-term register-prefetch (R10-proven, unchanged) ----
__device__ __forceinline__ void gemm_f16_2(
    const __half* __restrict__ Ah, const __half* __restrict__ Al,
    const __half* __restrict__ Bh,
    float* __restrict__ C, int N, int K)
{
    __shared__ __half sm[3 * 128 * SRW];   // 30720 bytes
    __half* sAh = sm;
    __half* sAl = sm + 128 * SRW;
    __half* sBh = sm + 2 * 128 * SRW;

    int tid  = threadIdx.x;
    int bm   = blockIdx.y * 128;
    int bn   = blockIdx.x * 128;
    int warp = tid >> 5, lane = tid & 31;
    int wm   = (warp & 1) * 64;
    int wn   = (warp >> 1) * 32;
    int g    = lane >> 2, tg = lane & 3;

    float acc[4][4][4];
#pragma unroll
    for (int i = 0; i < 4; ++i)
#pragma unroll
        for (int j = 0; j < 4; ++j)
#pragma unroll
            for (int v = 0; v < 4; ++v) acc[i][j][v] = 0.f;

    int row  = tid >> 1;
    int half = (tid & 1) * 16;
    const __half* gAh = Ah + (size_t)(bm + row) * K + half;
    const __half* gAl = Al + (size_t)(bm + row) * K + half;
    const __half* gBh = Bh + (size_t)(bn + row) * K + half;
    int sidx = row * SRW + half;

    uint4 pa0 = *(const uint4*)(gAh);
    uint4 pa1 = *(const uint4*)(gAh + 8);
    uint4 pl0 = *(const uint4*)(gAl);
    uint4 pl1 = *(const uint4*)(gAl + 8);
    uint4 pb0 = *(const uint4*)(gBh);
    uint4 pb1 = *(const uint4*)(gBh + 8);

    int nt = K / 32;
    for (int t = 0; t < nt; ++t) {
        __syncthreads();
        *(uint4*)(sAh + sidx)     = pa0;  *(uint4*)(sAh + sidx + 8) = pa1;
        *(uint4*)(sAl + sidx)     = pl0;  *(uint4*)(sAl + sidx + 8) = pl1;
        *(uint4*)(sBh + sidx)     = pb0;  *(uint4*)(sBh + sidx + 8) = pb1;
        __syncthreads();

        if (t + 1 < nt) {
            int k0 = (t + 1) * 32;
            pa0 = *(const uint4*)(gAh + k0);
            pa1 = *(const uint4*)(gAh + k0 + 8);
            pl0 = *(const uint4*)(gAl + k0);
            pl1 = *(const uint4*)(gAl + k0 + 8);
            pb0 = *(const uint4*)(gBh + k0);
            pb1 = *(const uint4*)(gBh + k0 + 8);
        }

#pragma unroll
        for (int ks = 0; ks < 2; ++ks) {
            int kk = ks * 16 + 2 * tg;
            uint32_t ah[4][4], al[4][4];
#pragma unroll
            for (int i = 0; i < 4; ++i) {
                int r0 = wm + i * 16 + g;
                ah[i][0] = *(const uint32_t*)&sAh[ r0      * SRW + kk];
                ah[i][1] = *(const uint32_t*)&sAh[(r0 + 8) * SRW + kk];
                ah[i][2] = *(const uint32_t*)&sAh[ r0      * SRW + kk + 8];
                ah[i][3] = *(const uint32_t*)&sAh[(r0 + 8) * SRW + kk + 8];
                al[i][0] = *(const uint32_t*)&sAl[ r0      * SRW + kk];
                al[i][1] = *(const uint32_t*)&sAl[(r0 + 8) * SRW + kk];
                al[i][2] = *(const uint32_t*)&sAl[ r0      * SRW + kk + 8];
                al[i][3] = *(const uint32_t*)&sAl[(r0 + 8) * SRW + kk + 8];
            }
#pragma unroll
            for (int j = 0; j < 4; ++j) {
                int n0 = wn + j * 8 + g;
                uint32_t bh0 = *(const uint32_t*)&sBh[n0 * SRW + kk];
                uint32_t bh1 = *(const uint32_t*)&sBh[n0 * SRW + kk + 8];
#pragma unroll
                for (int i = 0; i < 4; ++i) {
                    mma_f16(acc[i][j], ah[i], bh0, bh1);
                    mma_f16(acc[i][j], al[i], bh0, bh1);
                }
            }
        }
    }

#pragma unroll
    for (int i = 0; i < 4; ++i) {
        int r0 = bm + wm + i * 16 + g;
#pragma unroll
        for (int j = 0; j < 4; ++j) {
            int col = bn + wn + j * 8 + tg * 2;
            *(float2*)(C + (size_t)r0      * N + col) = make_float2(acc[i][j][0], acc[i][j][1]);
            *(float2*)(C + (size_t)(r0+8)  * N + col) = make_float2(acc[i][j][2], acc[i][j][3]);
        }
    }
}

__global__ __launch_bounds__(256) void gemm2_kernel(float* __restrict__ out) {
    gemm_f16_2(g_yh, g_yl, g_woh, out, KD, KD);
}

// ---------------- Phase A: per-chunk local scan from zero state ----------------
__global__ void scanA_kernel() {
    int d = blockIdx.x * 256 + threadIdx.x;
    int j = blockIdx.y, b = blockIdx.z;
    int ch0 = d * RANK;
    float2 a[RANK], bb[RANK], cc[RANK], s[RANK];
#pragma unroll
    for (int r = 0; r < RANK; ++r) {
        a[r] = g_ca[ch0 + r]; bb[r] = g_cb[ch0 + r]; cc[r] = g_cc[ch0 + r];
        s[r] = make_float2(0.f, 0.f);
    }
    int t0 = j * CL;
    const float4* up = (const float4*)(g_u + (size_t)(b * TLEN + t0) * N1 + d * (RANK * 2));
    float* yp = g_y + (size_t)(b * TLEN + t0) * D_MODEL + d;
    for (int t = 0; t < CL; ++t) {
        float4 u0 = up[0], u1 = up[1];
        float ur[4] = {u0.x, u0.z, u1.x, u1.z};
        float ui[4] = {u0.y, u0.w, u1.y, u1.w};
        float y = 0.f;
#pragma unroll
        for (int r = 0; r < RANK; ++r) {
            float bur = bb[r].x * ur[r] - bb[r].y * ui[r];
            float bui = bb[r].x * ui[r] + bb[r].y * ur[r];
            float sr  = a[r].x * s[r].x - a[r].y * s[r].y + bur;
            float si  = a[r].x * s[r].y + a[r].y * s[r].x + bui;
            s[r] = make_float2(sr, si);
            y += cc[r].x * sr - cc[r].y * si;
        }
        *yp = y;
        up += N1 / 4;
        yp += D_MODEL;
    }
    float2* sp = g_Sloc + (size_t)(b * NCHUNK + j) * NCH + ch0;
#pragma unroll
    for (int r = 0; r < RANK; ++r) sp[r] = s[r];
}

// ---------------- Phase B: sequential carry combine across chunks ----------------
__global__ void scanB_kernel() {
    int idx = blockIdx.x * 256 + threadIdx.x;
    if (idx >= BATCH * NCH) return;
    int b = idx / NCH, ch = idx % NCH;
    float2 aL = g_aL[ch];
    float2 carry = make_float2(0.f, 0.f);
    for (int j = 0; j < NCHUNK; ++j) {
        g_carry[(size_t)(b * NCHUNK + j) * NCH + ch] = carry;
        float2 S = g_Sloc[(size_t)(b * NCHUNK + j) * NCH + ch];
        carry = make_float2(aL.x * carry.x - aL.y * carry.y + S.x,
                            aL.x * carry.y + aL.y * carry.x + S.y);
    }
}

// ---------------- Phase C: y += Re(c * a^p * carry) ----------------
__global__ void scanC_kernel() {
    int d = blockIdx.x * 256 + threadIdx.x;
    int j = blockIdx.y + 1, b = blockIdx.z;
    int ch0 = d * RANK;
    float2 a[RANK], w[RANK];
#pragma unroll
    for (int r = 0; r < RANK; ++r) {
        a[r] = g_ca[ch0 + r];
        float2 carry = g_carry[(size_t)(b * NCHUNK + j) * NCH + ch0 + r];
        float2 c = g_cc[ch0 + r];
        w[r] = make_float2(c.x * carry.x - c.y * carry.y,
                           c.x * carry.y + c.y * carry.x);
    }
    int t0 = j * CL;
    float* yp = g_y + (size_t)(b * TLEN + t0) * D_MODEL + d;
    for (int t = 0; t < CL; ++t) {
        float corr = 0.f;
#pragma unroll
        for (int r = 0; r < RANK; ++r) {
            w[r] = make_float2(w[r].x * a[r].x - w[r].y * a[r].y,
                               w[r].x * a[r].y + w[r].y * a[r].x);
            corr += w[r].x;
        }
        *yp += corr;
        yp += D_MODEL;
    }
}

// ---------------- launch (no device symbols passed from host) ----------------
extern "C" void kernel_launch(void* const* d_in, const int* in_sizes, int n_in,
                              void* d_out, int out_size) {
    const float* x    = (const float*)d_in[0];
    const float* nw   = (const float*)d_in[1];
    const float* Win  = (const float*)d_in[2];
    const float* Wout = (const float*)d_in[3];
    const float* ap   = (const float*)d_in[4];
    const float* bp   = (const float*)d_in[5];
    const float* cp   = (const float*)d_in[6];
    float* out = (float*)d_out;

    coef_kernel<<<(NCH + 255) / 256, 256>>>(ap, bp, cp);
    round_win_kernel<<<(N1 * KD + 255) / 256, 256>>>(Win);
    round_wout_kernel<<<(KD * KD + 255) / 256, 256>>>(Wout);
    rmsnorm_kernel<<<MROWS, 256>>>(x, nw);
    gemm1_kernel<<<dim3(N1 / 128, MROWS / 128), 256>>>();
    scanA_kernel<<<dim3(D_MODEL / 256, NCHUNK, BATCH), 256>>>();
    scanB_kernel<<<(BATCH * NCH + 255) / 256, 256>>>();
    scanC_kernel<<<dim3(D_MODEL / 256, NCHUNK - 1, BATCH), 256>>>();
    split_y_kernel<<<(MROWS * KD + 255) / 256, 256>>>();
    gemm2_kernel<<<dim3(KD / 128, MROWS / 128), 256>>>(out);
}

// round 12
// speedup vs baseline: 3.5847x; 1.0452x over previous
#include <cuda_runtime.h>
#include <cuda_fp16.h>
#include <math.h>
#include <stdint.h>

#define D_MODEL 768
#define RANK 4
#define BATCH 2
#define TLEN 2048
#define MROWS (BATCH*TLEN)          // 4096
#define N1 (D_MODEL*RANK*2)         // 6144
#define KD D_MODEL                  // 768
#define NCH (D_MODEL*RANK)          // 3072
#define NCHUNK 128
#define CL (TLEN/NCHUNK)            // 16

// ---------------- scratch (static __device__, no allocations) ----------------
__device__ __half g_xh [MROWS*KD];                    // x rounded fp16
__device__ __half g_wih[N1*KD];                       // W_in  rounded fp16
__device__ __half g_woh[KD*KD];                       // W_out rounded fp16
__device__ __half g_yh [MROWS*KD], g_yl [MROWS*KD];   // y split hi/lo
__device__ __half g_u[MROWS*N1];                      // u in fp16 (48 MB)
__device__ float  g_y[MROWS*KD];
__device__ float2 g_ca[NCH], g_cb[NCH], g_cc[NCH], g_aL[NCH];
__device__ float2 g_Sloc [BATCH*NCHUNK*NCH];
__device__ float2 g_carry[BATCH*NCHUNK*NCH];

// ---------------- coefficient precompute ----------------
__global__ void coef_kernel(const float* __restrict__ ap,
                            const float* __restrict__ bp,
                            const float* __restrict__ cp) {
    int i = blockIdx.x * blockDim.x + threadIdx.x;
    if (i >= NCH) return;
    float2 a = make_float2(tanhf(ap[2*i]) * 0.97f, tanhf(ap[2*i+1]) * 0.97f);
    float2 b = make_float2(tanhf(bp[2*i]),         tanhf(bp[2*i+1]));
    float2 c = make_float2(tanhf(cp[2*i]),         tanhf(cp[2*i+1]));
    g_ca[i] = a; g_cb[i] = b; g_cc[i] = c;
    float2 p = a;
    for (int k = 1; k < CL; ++k)
        p = make_float2(p.x*a.x - p.y*a.y, p.x*a.y + p.y*a.x);
    g_aL[i] = p;
}

// ---------------- fp16 rounding ----------------
__global__ void round_win_kernel(const float* __restrict__ w) {
    int i = blockIdx.x * 256 + threadIdx.x;
    if (i < N1*KD) g_wih[i] = __float2half(w[i]);
}
__global__ void round_wout_kernel(const float* __restrict__ w) {
    int i = blockIdx.x * 256 + threadIdx.x;
    if (i < KD*KD) g_woh[i] = __float2half(w[i]);
}

// ---------------- RMSNorm -> fp16 ----------------
__global__ void rmsnorm_kernel(const float* __restrict__ x,
                               const float* __restrict__ w) {
    int row = blockIdx.x;
    const float* xr = x + (size_t)row * KD;
    float s = 0.f;
    for (int k = threadIdx.x; k < KD; k += 256) { float v = xr[k]; s += v * v; }
    __shared__ float red[256];
    red[threadIdx.x] = s; __syncthreads();
    for (int off = 128; off > 0; off >>= 1) {
        if (threadIdx.x < off) red[threadIdx.x] += red[threadIdx.x + off];
        __syncthreads();
    }
    float scale = rsqrtf(red[0] * (1.0f / KD) + 1e-6f);
    for (int k = threadIdx.x; k < KD; k += 256)
        g_xh[(size_t)row*KD + k] = __float2half(xr[k] * scale * w[k]);
}

// ============================================================================
// fp16 GEMMs, fp32 accum, mma.m16n8k16.  BM=BN=128, BK=32, 256 threads,
// warp grid 2x4, warp tile 64x32.  Fragment indexing proven R5/R7/R8/R10.
// gemm1: 1-term, cp.async double-buffered, lb(256,2), fp16 C output.
// gemm2: 2-term, cp.async single-buffered, lb(256,2)  (tail-wave fix).
// ============================================================================
#define SRW 40                       // smem row stride in fp16 (80B)
#define SSTG (2 * 128 * SRW)         // halves per stage (A tile + B tile)

__device__ __forceinline__ void mma_f16(float* c, const uint32_t* a,
                                        uint32_t b0, uint32_t b1) {
    asm volatile(
        "mma.sync.aligned.m16n8k16.row.col.f32.f16.f16.f32 "
        "{%0,%1,%2,%3}, {%4,%5,%6,%7}, {%8,%9}, {%0,%1,%2,%3};\n"
        : "+f"(c[0]), "+f"(c[1]), "+f"(c[2]), "+f"(c[3])
        : "r"(a[0]), "r"(a[1]), "r"(a[2]), "r"(a[3]), "r"(b0), "r"(b1));
}
__device__ __forceinline__ void cpa16(uint32_t s, const void* g) {
    asm volatile("cp.async.cg.shared.global [%0], [%1], 16;\n" :: "r"(s), "l"(g));
}

__global__ __launch_bounds__(256, 2) void gemm1_kernel() {
    const __half* __restrict__ Ah = g_xh;
    const __half* __restrict__ Bh = g_wih;
    __half* __restrict__ C = g_u;
    const int N = N1, K = KD;

    __shared__ __half sm[2 * SSTG];    // 40960 bytes (2 stages)

    int tid  = threadIdx.x;
    int bm   = blockIdx.y * 128;
    int bn   = blockIdx.x * 128;
    int warp = tid >> 5, lane = tid & 31;
    int wm   = (warp & 1) * 64;
    int wn   = (warp >> 1) * 32;
    int g    = lane >> 2, tg = lane & 3;

    float acc[4][4][4];
#pragma unroll
    for (int i = 0; i < 4; ++i)
#pragma unroll
        for (int j = 0; j < 4; ++j)
#pragma unroll
            for (int v = 0; v < 4; ++v) acc[i][j][v] = 0.f;

    int row  = tid >> 1;
    int half = (tid & 1) * 16;
    const __half* gA = Ah + (size_t)(bm + row) * K + half;
    const __half* gB = Bh + (size_t)(bn + row) * K + half;
    uint32_t sA = (uint32_t)__cvta_generic_to_shared(sm) + (uint32_t)(row * SRW + half) * 2u;
    uint32_t sB = sA + 128u * SRW * 2u;

    const int nt = K / 32;             // 24
#pragma unroll
    for (int st = 0; st < 2; ++st) {
        uint32_t off = (uint32_t)st * SSTG * 2u;
        int k0 = st * 32;
        cpa16(sA + off,      gA + k0);
        cpa16(sA + off + 16, gA + k0 + 8);
        cpa16(sB + off,      gB + k0);
        cpa16(sB + off + 16, gB + k0 + 8);
        asm volatile("cp.async.commit_group;\n");
    }

    for (int t = 0; t < nt; ++t) {
        if (t + 1 < nt) asm volatile("cp.async.wait_group 1;\n");
        else            asm volatile("cp.async.wait_group 0;\n");
        __syncthreads();

        const __half* As = sm + (t & 1) * SSTG;
        const __half* Bs = As + 128 * SRW;
#pragma unroll
        for (int ks = 0; ks < 2; ++ks) {
            int kk = ks * 16 + 2 * tg;
            uint32_t ah[4][4];
#pragma unroll
            for (int i = 0; i < 4; ++i) {
                int r0 = wm + i * 16 + g;
                ah[i][0] = *(const uint32_t*)&As[ r0      * SRW + kk];
                ah[i][1] = *(const uint32_t*)&As[(r0 + 8) * SRW + kk];
                ah[i][2] = *(const uint32_t*)&As[ r0      * SRW + kk + 8];
                ah[i][3] = *(const uint32_t*)&As[(r0 + 8) * SRW + kk + 8];
            }
#pragma unroll
            for (int j = 0; j < 4; ++j) {
                int n0 = wn + j * 8 + g;
                uint32_t bh0 = *(const uint32_t*)&Bs[n0 * SRW + kk];
                uint32_t bh1 = *(const uint32_t*)&Bs[n0 * SRW + kk + 8];
#pragma unroll
                for (int i = 0; i < 4; ++i)
                    mma_f16(acc[i][j], ah[i], bh0, bh1);
            }
        }
        __syncthreads();
        if (t + 2 < nt) {
            uint32_t off = (uint32_t)(t & 1) * SSTG * 2u;
            int k0 = (t + 2) * 32;
            cpa16(sA + off,      gA + k0);
            cpa16(sA + off + 16, gA + k0 + 8);
            cpa16(sB + off,      gB + k0);
            cpa16(sB + off + 16, gB + k0 + 8);
            asm volatile("cp.async.commit_group;\n");
        }
    }

    // epilogue: fp16 output
#pragma unroll
    for (int i = 0; i < 4; ++i) {
        int r0 = bm + wm + i * 16 + g;
#pragma unroll
        for (int j = 0; j < 4; ++j) {
            int col = bn + wn + j * 8 + tg * 2;
            *(__half2*)(C + (size_t)r0      * N + col) = __floats2half2_rn(acc[i][j][0], acc[i][j][1]);
            *(__half2*)(C + (size_t)(r0+8)  * N + col) = __floats2half2_rn(acc[i][j][2], acc[i][j][3]);
        }
    }
}

// ---- gemm2: 2-term, cp.async single-buffered, 2 CTAs/SM ----
__global__ __launch_bounds__(256, 2) void gemm2_kernel(float* __restrict__ out) {
    const __half* __restrict__ Ah = g_yh;
    const __half* __restrict__ Al = g_yl;
    const __half* __restrict__ Bh = g_woh;
    float* __restrict__ C = out;
    const int N = KD, K = KD;

    __shared__ __half sm[3 * 128 * SRW];   // 30720 bytes

    int tid  = threadIdx.x;
    int bm   = blockIdx.y * 128;
    int bn   = blockIdx.x * 128;
    int warp = tid >> 5, lane = tid & 31;
    int wm   = (warp & 1) * 64;
    int wn   = (warp >> 1) * 32;
    int g    = lane >> 2, tg = lane & 3;

    float acc[4][4][4];
#pragma unroll
    for (int i = 0; i < 4; ++i)
#pragma unroll
        for (int j = 0; j < 4; ++j)
#pragma unroll
            for (int v = 0; v < 4; ++v) acc[i][j][v] = 0.f;

    int row  = tid >> 1;
    int half = (tid & 1) * 16;
    const __half* gAh = Ah + (size_t)(bm + row) * K + half;
    const __half* gAl = Al + (size_t)(bm + row) * K + half;
    const __half* gBh = Bh + (size_t)(bn + row) * K + half;
    uint32_t sA = (uint32_t)__cvta_generic_to_shared(sm) + (uint32_t)(row * SRW + half) * 2u;
    uint32_t sL = sA + 128u * SRW * 2u;
    uint32_t sB = sA + 2u * 128u * SRW * 2u;
    const __half* sAh = sm;
    const __half* sAl = sm + 128 * SRW;
    const __half* sBh = sm + 2 * 128 * SRW;

    int nt = K / 32;
    for (int t = 0; t < nt; ++t) {
        int k0 = t * 32;
        __syncthreads();                      // previous compute done
        cpa16(sA,      gAh + k0);  cpa16(sA + 16, gAh + k0 + 8);
        cpa16(sL,      gAl + k0);  cpa16(sL + 16, gAl + k0 + 8);
        cpa16(sB,      gBh + k0);  cpa16(sB + 16, gBh + k0 + 8);
        asm volatile("cp.async.commit_group;\n");
        asm volatile("cp.async.wait_group 0;\n");
        __syncthreads();

#pragma unroll
        for (int ks = 0; ks < 2; ++ks) {
            int kk = ks * 16 + 2 * tg;
            uint32_t ah[4][4], al[4][4];
#pragma unroll
            for (int i = 0; i < 4; ++i) {
                int r0 = wm + i * 16 + g;
                ah[i][0] = *(const uint32_t*)&sAh[ r0      * SRW + kk];
                ah[i][1] = *(const uint32_t*)&sAh[(r0 + 8) * SRW + kk];
                ah[i][2] = *(const uint32_t*)&sAh[ r0      * SRW + kk + 8];
                ah[i][3] = *(const uint32_t*)&sAh[(r0 + 8) * SRW + kk + 8];
                al[i][0] = *(const uint32_t*)&sAl[ r0      * SRW + kk];
                al[i][1] = *(const uint32_t*)&sAl[(r0 + 8) * SRW + kk];
                al[i][2] = *(const uint32_t*)&sAl[ r0      * SRW + kk + 8];
                al[i][3] = *(const uint32_t*)&sAl[(r0 + 8) * SRW + kk + 8];
            }
#pragma unroll
            for (int j = 0; j < 4; ++j) {
                int n0 = wn + j * 8 + g;
                uint32_t bh0 = *(const uint32_t*)&sBh[n0 * SRW + kk];
                uint32_t bh1 = *(const uint32_t*)&sBh[n0 * SRW + kk + 8];
#pragma unroll
                for (int i = 0; i < 4; ++i) {
                    mma_f16(acc[i][j], ah[i], bh0, bh1);
                    mma_f16(acc[i][j], al[i], bh0, bh1);
                }
            }
        }
    }

#pragma unroll
    for (int i = 0; i < 4; ++i) {
        int r0 = bm + wm + i * 16 + g;
#pragma unroll
        for (int j = 0; j < 4; ++j) {
            int col = bn + wn + j * 8 + tg * 2;
            *(float2*)(C + (size_t)r0      * N + col) = make_float2(acc[i][j][0], acc[i][j][1]);
            *(float2*)(C + (size_t)(r0+8)  * N + col) = make_float2(acc[i][j][2], acc[i][j][3]);
        }
    }
}

// ---------------- Phase A: per-chunk local scan (u in fp16) ----------------
__global__ void scanA_kernel() {
    int d = blockIdx.x * 256 + threadIdx.x;
    int j = blockIdx.y, b = blockIdx.z;
    int ch0 = d * RANK;
    float2 a[RANK], bb[RANK], cc[RANK], s[RANK];
#pragma unroll
    for (int r = 0; r < RANK; ++r) {
        a[r] = g_ca[ch0 + r]; bb[r] = g_cb[ch0 + r]; cc[r] = g_cc[ch0 + r];
        s[r] = make_float2(0.f, 0.f);
    }
    int t0 = j * CL;
    const uint4* up = (const uint4*)(g_u + (size_t)(b * TLEN + t0) * N1 + d * (RANK * 2));
    float* yp = g_y + (size_t)(b * TLEN + t0) * D_MODEL + d;
    for (int t = 0; t < CL; ++t) {
        uint4 v = *up;                        // 8 halves = 4 complex
        const __half2* ph = (const __half2*)&v;
        float y = 0.f;
#pragma unroll
        for (int r = 0; r < RANK; ++r) {
            float2 uc = __half22float2(ph[r]);   // (re, im)
            float bur = bb[r].x * uc.x - bb[r].y * uc.y;
            float bui = bb[r].x * uc.y + bb[r].y * uc.x;
            float sr  = a[r].x * s[r].x - a[r].y * s[r].y + bur;
            float si  = a[r].x * s[r].y + a[r].y * s[r].x + bui;
            s[r] = make_float2(sr, si);
            y += cc[r].x * sr - cc[r].y * si;
        }
        *yp = y;
        up += N1 / 8;
        yp += D_MODEL;
    }
    float2* sp = g_Sloc + (size_t)(b * NCHUNK + j) * NCH + ch0;
#pragma unroll
    for (int r = 0; r < RANK; ++r) sp[r] = s[r];
}

// ---------------- Phase B: sequential carry combine across chunks ----------------
__global__ void scanB_kernel() {
    int idx = blockIdx.x * 256 + threadIdx.x;
    if (idx >= BATCH * NCH) return;
    int b = idx / NCH, ch = idx % NCH;
    float2 aL = g_aL[ch];
    float2 carry = make_float2(0.f, 0.f);
    for (int j = 0; j < NCHUNK; ++j) {
        g_carry[(size_t)(b * NCHUNK + j) * NCH + ch] = carry;
        float2 S = g_Sloc[(size_t)(b * NCHUNK + j) * NCH + ch];
        carry = make_float2(aL.x * carry.x - aL.y * carry.y + S.x,
                            aL.x * carry.y + aL.y * carry.x + S.y);
    }
}

// ---------------- Phase C: y += Re(c*a^p*carry); split y -> yh/yl (all chunks) --
__global__ void scanC_kernel() {
    int d = blockIdx.x * 256 + threadIdx.x;
    int j = blockIdx.y, b = blockIdx.z;       // j = 0..NCHUNK-1 (j=0: carry=0 -> pure split)
    int ch0 = d * RANK;
    float2 a[RANK], w[RANK];
#pragma unroll
    for (int r = 0; r < RANK; ++r) {
        a[r] = g_ca[ch0 + r];
        float2 carry = g_carry[(size_t)(b * NCHUNK + j) * NCH + ch0 + r];
        float2 c = g_cc[ch0 + r];
        w[r] = make_float2(c.x * carry.x - c.y * carry.y,
                           c.x * carry.y + c.y * carry.x);
    }
    int t0 = j * CL;
    size_t idx = (size_t)(b * TLEN + t0) * D_MODEL + d;
    for (int t = 0; t < CL; ++t) {
        float corr = 0.f;
#pragma unroll
        for (int r = 0; r < RANK; ++r) {
            w[r] = make_float2(w[r].x * a[r].x - w[r].y * a[r].y,
                               w[r].x * a[r].y + w[r].y * a[r].x);
            corr += w[r].x;
        }
        float yv = g_y[idx] + corr;
        __half h = __float2half(yv);
        g_yh[idx] = h;
        g_yl[idx] = __float2half(yv - __half2float(h));
        idx += D_MODEL;
    }
}

// ---------------- launch (no device symbols passed from host) ----------------
extern "C" void kernel_launch(void* const* d_in, const int* in_sizes, int n_in,
                              void* d_out, int out_size) {
    const float* x    = (const float*)d_in[0];
    const float* nw   = (const float*)d_in[1];
    const float* Win  = (const float*)d_in[2];
    const float* Wout = (const float*)d_in[3];
    const float* ap   = (const float*)d_in[4];
    const float* bp   = (const float*)d_in[5];
    const float* cp   = (const float*)d_in[6];
    float* out = (float*)d_out;

    coef_kernel<<<(NCH + 255) / 256, 256>>>(ap, bp, cp);
    round_win_kernel<<<(N1 * KD + 255) / 256, 256>>>(Win);
    round_wout_kernel<<<(KD * KD + 255) / 256, 256>>>(Wout);
    rmsnorm_kernel<<<MROWS, 256>>>(x, nw);
    gemm1_kernel<<<dim3(N1 / 128, MROWS / 128), 256>>>();
    scanA_kernel<<<dim3(D_MODEL / 256, NCHUNK, BATCH), 256>>>();
    scanB_kernel<<<(BATCH * NCH + 255) / 256, 256>>>();
    scanC_kernel<<<dim3(D_MODEL / 256, NCHUNK, BATCH), 256>>>();
    gemm2_kernel<<<dim3(KD / 128, MROWS / 128), 256>>>(out);
}

// round 13
// speedup vs baseline: 3.9307x; 1.0965x over previous
#include <cuda_runtime.h>
#include <cuda_fp16.h>
#include <math.h>
#include <stdint.h>

#define D_MODEL 768
#define RANK 4
#define BATCH 2
#define TLEN 2048
#define MROWS (BATCH*TLEN)          // 4096
#define N1 (D_MODEL*RANK*2)         // 6144
#define KD D_MODEL                  // 768
#define NCH (D_MODEL*RANK)          // 3072
#define NCHUNK 128
#define CL (TLEN/NCHUNK)            // 16

// ---------------- scratch (static __device__, no allocations) ----------------
__device__ __half g_xh [MROWS*KD];                    // x rounded fp16
__device__ __half g_wih[N1*KD];                       // W_in  rounded fp16
__device__ __half g_woh[KD*KD];                       // W_out rounded fp16
__device__ __half g_yh [MROWS*KD];                    // y rounded fp16
__device__ __half g_u[MROWS*N1];                      // u in fp16 (48 MB)
__device__ float  g_y[MROWS*KD];
__device__ float2 g_ca[NCH], g_cb[NCH], g_cc[NCH], g_aL[NCH];
__device__ float2 g_Sloc [BATCH*NCHUNK*NCH];
__device__ float2 g_carry[BATCH*NCHUNK*NCH];

// ---------------- coefficient precompute ----------------
__global__ void coef_kernel(const float* __restrict__ ap,
                            const float* __restrict__ bp,
                            const float* __restrict__ cp) {
    int i = blockIdx.x * blockDim.x + threadIdx.x;
    if (i >= NCH) return;
    float2 a = make_float2(tanhf(ap[2*i]) * 0.97f, tanhf(ap[2*i+1]) * 0.97f);
    float2 b = make_float2(tanhf(bp[2*i]),         tanhf(bp[2*i+1]));
    float2 c = make_float2(tanhf(cp[2*i]),         tanhf(cp[2*i+1]));
    g_ca[i] = a; g_cb[i] = b; g_cc[i] = c;
    float2 p = a;
    for (int k = 1; k < CL; ++k)
        p = make_float2(p.x*a.x - p.y*a.y, p.x*a.y + p.y*a.x);
    g_aL[i] = p;
}

// ---------------- fp16 rounding of both weight matrices (one launch) --------
__global__ void round_w_kernel(const float* __restrict__ win,
                               const float* __restrict__ wout) {
    int i = blockIdx.x * 256 + threadIdx.x;
    if (i < N1*KD) {
        g_wih[i] = __float2half(win[i]);
    } else if (i < N1*KD + KD*KD) {
        int j = i - N1*KD;
        g_woh[j] = __float2half(wout[j]);
    }
}

// ---------------- RMSNorm -> fp16 ----------------
__global__ void rmsnorm_kernel(const float* __restrict__ x,
                               const float* __restrict__ w) {
    int row = blockIdx.x;
    const float* xr = x + (size_t)row * KD;
    float s = 0.f;
    for (int k = threadIdx.x; k < KD; k += 256) { float v = xr[k]; s += v * v; }
    __shared__ float red[256];
    red[threadIdx.x] = s; __syncthreads();
    for (int off = 128; off > 0; off >>= 1) {
        if (threadIdx.x < off) red[threadIdx.x] += red[threadIdx.x + off];
        __syncthreads();
    }
    float scale = rsqrtf(red[0] * (1.0f / KD) + 1e-6f);
    for (int k = threadIdx.x; k < KD; k += 256)
        g_xh[(size_t)row*KD + k] = __float2half(xr[k] * scale * w[k]);
}

// ============================================================================
// fp16 1-term GEMM, fp32 accum, mma.m16n8k16.  BM=BN=128, BK=32, 256 threads,
// warp grid 2x4, warp tile 64x32, cp.async double-buffered, lb(256,2).
// Fragment indexing proven R5/R7/R8/R10/R11.
// gemm1: C fp16 (g_u).   gemm2: C fp32 (out).
// ============================================================================
#define SRW 40                       // smem row stride in fp16 (80B)
#define SSTG (2 * 128 * SRW)         // halves per stage (A tile + B tile)

__device__ __forceinline__ void mma_f16(float* c, const uint32_t* a,
                                        uint32_t b0, uint32_t b1) {
    asm volatile(
        "mma.sync.aligned.m16n8k16.row.col.f32.f16.f16.f32 "
        "{%0,%1,%2,%3}, {%4,%5,%6,%7}, {%8,%9}, {%0,%1,%2,%3};\n"
        : "+f"(c[0]), "+f"(c[1]), "+f"(c[2]), "+f"(c[3])
        : "r"(a[0]), "r"(a[1]), "r"(a[2]), "r"(a[3]), "r"(b0), "r"(b1));
}
__device__ __forceinline__ void cpa16(uint32_t s, const void* g) {
    asm volatile("cp.async.cg.shared.global [%0], [%1], 16;\n" :: "r"(s), "l"(g));
}

// core: accumulates the 64x32-per-warp tile; epilogue handled by caller lambda-style
__device__ __forceinline__ void gemm_1t_core(
    const __half* __restrict__ Ah, const __half* __restrict__ Bh,
    int N, int K, float acc[4][4][4], __half* smbase)
{
    int tid  = threadIdx.x;
    int bm   = blockIdx.y * 128;
    int bn   = blockIdx.x * 128;
    int warp = tid >> 5, lane = tid & 31;
    int wm   = (warp & 1) * 64;
    int wn   = (warp >> 1) * 32;
    int g    = lane >> 2, tg = lane & 3;

    int row  = tid >> 1;
    int half = (tid & 1) * 16;
    const __half* gA = Ah + (size_t)(bm + row) * K + half;
    const __half* gB = Bh + (size_t)(bn + row) * K + half;
    uint32_t sA = (uint32_t)__cvta_generic_to_shared(smbase) + (uint32_t)(row * SRW + half) * 2u;
    uint32_t sB = sA + 128u * SRW * 2u;

    const int nt = K / 32;
#pragma unroll
    for (int st = 0; st < 2; ++st) {
        uint32_t off = (uint32_t)st * SSTG * 2u;
        int k0 = st * 32;
        cpa16(sA + off,      gA + k0);
        cpa16(sA + off + 16, gA + k0 + 8);
        cpa16(sB + off,      gB + k0);
        cpa16(sB + off + 16, gB + k0 + 8);
        asm volatile("cp.async.commit_group;\n");
    }

    for (int t = 0; t < nt; ++t) {
        if (t + 1 < nt) asm volatile("cp.async.wait_group 1;\n");
        else            asm volatile("cp.async.wait_group 0;\n");
        __syncthreads();

        const __half* As = smbase + (t & 1) * SSTG;
        const __half* Bs = As + 128 * SRW;
#pragma unroll
        for (int ks = 0; ks < 2; ++ks) {
            int kk = ks * 16 + 2 * tg;
            uint32_t ah[4][4];
#pragma unroll
            for (int i = 0; i < 4; ++i) {
                int r0 = wm + i * 16 + g;
                ah[i][0] = *(const uint32_t*)&As[ r0      * SRW + kk];
                ah[i][1] = *(const uint32_t*)&As[(r0 + 8) * SRW + kk];
                ah[i][2] = *(const uint32_t*)&As[ r0      * SRW + kk + 8];
                ah[i][3] = *(const uint32_t*)&As[(r0 + 8) * SRW + kk + 8];
            }
#pragma unroll
            for (int j = 0; j < 4; ++j) {
                int n0 = wn + j * 8 + g;
                uint32_t bh0 = *(const uint32_t*)&Bs[n0 * SRW + kk];
                uint32_t bh1 = *(const uint32_t*)&Bs[n0 * SRW + kk + 8];
#pragma unroll
                for (int i = 0; i < 4; ++i)
                    mma_f16(acc[i][j], ah[i], bh0, bh1);
            }
        }
        __syncthreads();
        if (t + 2 < nt) {
            uint32_t off = (uint32_t)(t & 1) * SSTG * 2u;
            int k0 = (t + 2) * 32;
            cpa16(sA + off,      gA + k0);
            cpa16(sA + off + 16, gA + k0 + 8);
            cpa16(sB + off,      gB + k0);
            cpa16(sB + off + 16, gB + k0 + 8);
            asm volatile("cp.async.commit_group;\n");
        }
    }
}

__global__ __launch_bounds__(256, 2) void gemm1_kernel() {
    __shared__ __half sm[2 * SSTG];    // 40960 bytes
    float acc[4][4][4];
#pragma unroll
    for (int i = 0; i < 4; ++i)
#pragma unroll
        for (int j = 0; j < 4; ++j)
#pragma unroll
            for (int v = 0; v < 4; ++v) acc[i][j][v] = 0.f;

    gemm_1t_core(g_xh, g_wih, N1, KD, acc, sm);

    int tid = threadIdx.x, warp = tid >> 5, lane = tid & 31;
    int wm = (warp & 1) * 64, wn = (warp >> 1) * 32;
    int g = lane >> 2, tg = lane & 3;
    int bm = blockIdx.y * 128, bn = blockIdx.x * 128;
#pragma unroll
    for (int i = 0; i < 4; ++i) {
        int r0 = bm + wm + i * 16 + g;
#pragma unroll
        for (int j = 0; j < 4; ++j) {
            int col = bn + wn + j * 8 + tg * 2;
            *(__half2*)(g_u + (size_t)r0      * N1 + col) = __floats2half2_rn(acc[i][j][0], acc[i][j][1]);
            *(__half2*)(g_u + (size_t)(r0+8)  * N1 + col) = __floats2half2_rn(acc[i][j][2], acc[i][j][3]);
        }
    }
}

__global__ __launch_bounds__(256, 2) void gemm2_kernel(float* __restrict__ out) {
    __shared__ __half sm[2 * SSTG];    // 40960 bytes
    float acc[4][4][4];
#pragma unroll
    for (int i = 0; i < 4; ++i)
#pragma unroll
        for (int j = 0; j < 4; ++j)
#pragma unroll
            for (int v = 0; v < 4; ++v) acc[i][j][v] = 0.f;

    gemm_1t_core(g_yh, g_woh, KD, KD, acc, sm);

    int tid = threadIdx.x, warp = tid >> 5, lane = tid & 31;
    int wm = (warp & 1) * 64, wn = (warp >> 1) * 32;
    int g = lane >> 2, tg = lane & 3;
    int bm = blockIdx.y * 128, bn = blockIdx.x * 128;
#pragma unroll
    for (int i = 0; i < 4; ++i) {
        int r0 = bm + wm + i * 16 + g;
#pragma unroll
        for (int j = 0; j < 4; ++j) {
            int col = bn + wn + j * 8 + tg * 2;
            *(float2*)(out + (size_t)r0      * KD + col) = make_float2(acc[i][j][0], acc[i][j][1]);
            *(float2*)(out + (size_t)(r0+8)  * KD + col) = make_float2(acc[i][j][2], acc[i][j][3]);
        }
    }
}

// ---------------- Phase A: per-chunk local scan (u fp16, prefetched) --------
__global__ void scanA_kernel() {
    int d = blockIdx.x * 256 + threadIdx.x;
    int j = blockIdx.y, b = blockIdx.z;
    int ch0 = d * RANK;
    float2 a[RANK], bb[RANK], cc[RANK], s[RANK];
#pragma unroll
    for (int r = 0; r < RANK; ++r) {
        a[r] = g_ca[ch0 + r]; bb[r] = g_cb[ch0 + r]; cc[r] = g_cc[ch0 + r];
        s[r] = make_float2(0.f, 0.f);
    }
    int t0 = j * CL;
    const uint4* up = (const uint4*)(g_u + (size_t)(b * TLEN + t0) * N1 + d * (RANK * 2));
    float* yp = g_y + (size_t)(b * TLEN + t0) * D_MODEL + d;
    uint4 v = *up;
    for (int t = 0; t < CL; ++t) {
        up += N1 / 8;
        uint4 vn;
        if (t + 1 < CL) vn = *up;            // prefetch next before compute
        const __half2* ph = (const __half2*)&v;
        float y = 0.f;
#pragma unroll
        for (int r = 0; r < RANK; ++r) {
            float2 uc = __half22float2(ph[r]);
            float bur = bb[r].x * uc.x - bb[r].y * uc.y;
            float bui = bb[r].x * uc.y + bb[r].y * uc.x;
            float sr  = a[r].x * s[r].x - a[r].y * s[r].y + bur;
            float si  = a[r].x * s[r].y + a[r].y * s[r].x + bui;
            s[r] = make_float2(sr, si);
            y += cc[r].x * sr - cc[r].y * si;
        }
        *yp = y;
        yp += D_MODEL;
        v = vn;
    }
    float2* sp = g_Sloc + (size_t)(b * NCHUNK + j) * NCH + ch0;
#pragma unroll
    for (int r = 0; r < RANK; ++r) sp[r] = s[r];
}

// ---------------- Phase B: sequential carry combine across chunks ----------------
__global__ void scanB_kernel() {
    int idx = blockIdx.x * 256 + threadIdx.x;
    if (idx >= BATCH * NCH) return;
    int b = idx / NCH, ch = idx % NCH;
    float2 aL = g_aL[ch];
    float2 carry = make_float2(0.f, 0.f);
    for (int j = 0; j < NCHUNK; ++j) {
        g_carry[(size_t)(b * NCHUNK + j) * NCH + ch] = carry;
        float2 S = g_Sloc[(size_t)(b * NCHUNK + j) * NCH + ch];
        carry = make_float2(aL.x * carry.x - aL.y * carry.y + S.x,
                            aL.x * carry.y + aL.y * carry.x + S.y);
    }
}

// ---------------- Phase C: y += Re(c*a^p*carry) -> fp16 yh (all chunks) -----
__global__ void scanC_kernel() {
    int d = blockIdx.x * 256 + threadIdx.x;
    int j = blockIdx.y, b = blockIdx.z;       // j=0: carry=0 -> pure round
    int ch0 = d * RANK;
    float2 a[RANK], w[RANK];
#pragma unroll
    for (int r = 0; r < RANK; ++r) {
        a[r] = g_ca[ch0 + r];
        float2 carry = g_carry[(size_t)(b * NCHUNK + j) * NCH + ch0 + r];
        float2 c = g_cc[ch0 + r];
        w[r] = make_float2(c.x * carry.x - c.y * carry.y,
                           c.x * carry.y + c.y * carry.x);
    }
    int t0 = j * CL;
    size_t idx = (size_t)(b * TLEN + t0) * D_MODEL + d;
    for (int t = 0; t < CL; ++t) {
        float corr = 0.f;
#pragma unroll
        for (int r = 0; r < RANK; ++r) {
            w[r] = make_float2(w[r].x * a[r].x - w[r].y * a[r].y,
                               w[r].x * a[r].y + w[r].y * a[r].x);
            corr += w[r].x;
        }
        g_yh[idx] = __float2half(g_y[idx] + corr);
        idx += D_MODEL;
    }
}

// ---------------- launch (no device symbols passed from host) ----------------
extern "C" void kernel_launch(void* const* d_in, const int* in_sizes, int n_in,
                              void* d_out, int out_size) {
    const float* x    = (const float*)d_in[0];
    const float* nw   = (const float*)d_in[1];
    const float* Win  = (const float*)d_in[2];
    const float* Wout = (const float*)d_in[3];
    const float* ap   = (const float*)d_in[4];
    const float* bp   = (const float*)d_in[5];
    const float* cp   = (const float*)d_in[6];
    float* out = (float*)d_out;

    coef_kernel<<<(NCH + 255) / 256, 256>>>(ap, bp, cp);
    round_w_kernel<<<(N1 * KD + KD * KD + 255) / 256, 256>>>(Win, Wout);
    rmsnorm_kernel<<<MROWS, 256>>>(x, nw);
    gemm1_kernel<<<dim3(N1 / 128, MROWS / 128), 256>>>();
    scanA_kernel<<<dim3(D_MODEL / 256, NCHUNK, BATCH), 256>>>();
    scanB_kernel<<<(BATCH * NCH + 255) / 256, 256>>>();
    scanC_kernel<<<dim3(D_MODEL / 256, NCHUNK, BATCH), 256>>>();
    gemm2_kernel<<<dim3(KD / 128, MROWS / 128), 256>>>(out);
}

// round 14
// speedup vs baseline: 3.9520x; 1.0054x over previous
#include <cuda_runtime.h>
#include <cuda_fp16.h>
#include <math.h>
#include <stdint.h>

#define D_MODEL 768
#define RANK 4
#define BATCH 2
#define TLEN 2048
#define MROWS (BATCH*TLEN)          // 4096
#define N1 (D_MODEL*RANK*2)         // 6144
#define KD D_MODEL                  // 768
#define NCH (D_MODEL*RANK)          // 3072
#define NCHUNK 128
#define CL (TLEN/NCHUNK)            // 16

// ---------------- scratch (static __device__, no allocations) ----------------
__device__ __half g_xh [MROWS*KD];                    // x rounded fp16
__device__ __half g_wih[N1*KD];                       // W_in  rounded fp16
__device__ __half g_woh[KD*KD];                       // W_out rounded fp16
__device__ __half g_yh [MROWS*KD];                    // y rounded fp16
__device__ __half g_u[MROWS*N1];                      // u in fp16 (48 MB)
__device__ float  g_y[MROWS*KD];
__device__ float2 g_ca[NCH], g_cb[NCH], g_cc[NCH], g_aL[NCH];
__device__ float2 g_Sloc [BATCH*NCHUNK*NCH];
__device__ float2 g_carry[BATCH*NCHUNK*NCH];

// ---------------- coefficient precompute ----------------
__global__ void coef_kernel(const float* __restrict__ ap,
                            const float* __restrict__ bp,
                            const float* __restrict__ cp) {
    int i = blockIdx.x * blockDim.x + threadIdx.x;
    if (i >= NCH) return;
    float2 a = make_float2(tanhf(ap[2*i]) * 0.97f, tanhf(ap[2*i+1]) * 0.97f);
    float2 b = make_float2(tanhf(bp[2*i]),         tanhf(bp[2*i+1]));
    float2 c = make_float2(tanhf(cp[2*i]),         tanhf(cp[2*i+1]));
    g_ca[i] = a; g_cb[i] = b; g_cc[i] = c;
    float2 p = a;
    for (int k = 1; k < CL; ++k)
        p = make_float2(p.x*a.x - p.y*a.y, p.x*a.y + p.y*a.x);
    g_aL[i] = p;
}

// ---------------- fp16 rounding of both weight matrices (one launch) --------
__global__ void round_w_kernel(const float* __restrict__ win,
                               const float* __restrict__ wout) {
    int i = blockIdx.x * 256 + threadIdx.x;
    if (i < N1*KD) {
        g_wih[i] = __float2half(win[i]);
    } else if (i < N1*KD + KD*KD) {
        int j = i - N1*KD;
        g_woh[j] = __float2half(wout[j]);
    }
}

// ---------------- RMSNorm -> fp16 ----------------
__global__ void rmsnorm_kernel(const float* __restrict__ x,
                               const float* __restrict__ w) {
    int row = blockIdx.x;
    const float* xr = x + (size_t)row * KD;
    float s = 0.f;
    for (int k = threadIdx.x; k < KD; k += 256) { float v = xr[k]; s += v * v; }
    __shared__ float red[256];
    red[threadIdx.x] = s; __syncthreads();
    for (int off = 128; off > 0; off >>= 1) {
        if (threadIdx.x < off) red[threadIdx.x] += red[threadIdx.x + off];
        __syncthreads();
    }
    float scale = rsqrtf(red[0] * (1.0f / KD) + 1e-6f);
    for (int k = threadIdx.x; k < KD; k += 256)
        g_xh[(size_t)row*KD + k] = __float2half(xr[k] * scale * w[k]);
}

// ============================================================================
// fp16 1-term GEMM, fp32 accum, mma.m16n8k16.  BM=BN=128, BK=32, 256 threads,
// warp grid 2x4, warp tile 64x32.  3-stage cp.async pipeline with ONE
// __syncthreads per k-tile (dynamic smem, 60KB).  lb(256,2).
// Fragment indexing proven R5/R7/R8/R10-R12.
// ============================================================================
#define SRW 40                       // smem row stride in fp16 (80B)
#define SSTG (2 * 128 * SRW)         // halves per stage (A tile + B tile)
#define NSTAGE 3
#define GEMM_SMEM (NSTAGE * SSTG * 2)   // 61440 bytes

__device__ __forceinline__ void mma_f16(float* c, const uint32_t* a,
                                        uint32_t b0, uint32_t b1) {
    asm volatile(
        "mma.sync.aligned.m16n8k16.row.col.f32.f16.f16.f32 "
        "{%0,%1,%2,%3}, {%4,%5,%6,%7}, {%8,%9}, {%0,%1,%2,%3};\n"
        : "+f"(c[0]), "+f"(c[1]), "+f"(c[2]), "+f"(c[3])
        : "r"(a[0]), "r"(a[1]), "r"(a[2]), "r"(a[3]), "r"(b0), "r"(b1));
}
__device__ __forceinline__ void cpa16(uint32_t s, const void* g) {
    asm volatile("cp.async.cg.shared.global [%0], [%1], 16;\n" :: "r"(s), "l"(g));
}

__device__ __forceinline__ void gemm_1t_core(
    const __half* __restrict__ Ah, const __half* __restrict__ Bh,
    int N, int K, float acc[4][4][4], __half* smbase)
{
    int tid  = threadIdx.x;
    int bm   = blockIdx.y * 128;
    int bn   = blockIdx.x * 128;
    int warp = tid >> 5, lane = tid & 31;
    int wm   = (warp & 1) * 64;
    int wn   = (warp >> 1) * 32;
    int g    = lane >> 2, tg = lane & 3;

    int row  = tid >> 1;
    int half = (tid & 1) * 16;
    const __half* gA = Ah + (size_t)(bm + row) * K + half;
    const __half* gB = Bh + (size_t)(bn + row) * K + half;
    uint32_t sA = (uint32_t)__cvta_generic_to_shared(smbase) + (uint32_t)(row * SRW + half) * 2u;
    uint32_t sB = sA + 128u * SRW * 2u;

    const int nt = K / 32;             // 24
    // prologue: stages 0,1 into buffers 0,1
#pragma unroll
    for (int st = 0; st < 2; ++st) {
        uint32_t off = (uint32_t)st * SSTG * 2u;
        int k0 = st * 32;
        cpa16(sA + off,      gA + k0);
        cpa16(sA + off + 16, gA + k0 + 8);
        cpa16(sB + off,      gB + k0);
        cpa16(sB + off + 16, gB + k0 + 8);
        asm volatile("cp.async.commit_group;\n");
    }

    int cbuf = 0;   // buffer holding stage t
    int ibuf = 2;   // buffer to fill with stage t+2
    for (int t = 0; t < nt; ++t) {
        asm volatile("cp.async.wait_group 1;\n");   // stage t resident
        __syncthreads();                            // ONE barrier per tile

        // issue stage t+2 into ibuf (consumed at t-1; barrier ordered)
        if (t + 2 < nt) {
            uint32_t off = (uint32_t)ibuf * SSTG * 2u;
            int k0 = (t + 2) * 32;
            cpa16(sA + off,      gA + k0);
            cpa16(sA + off + 16, gA + k0 + 8);
            cpa16(sB + off,      gB + k0);
            cpa16(sB + off + 16, gB + k0 + 8);
        }
        asm volatile("cp.async.commit_group;\n");   // commit EVERY iter (may be empty)

        const __half* As = smbase + cbuf * SSTG;
        const __half* Bs = As + 128 * SRW;
#pragma unroll
        for (int ks = 0; ks < 2; ++ks) {
            int kk = ks * 16 + 2 * tg;
            uint32_t ah[4][4];
#pragma unroll
            for (int i = 0; i < 4; ++i) {
                int r0 = wm + i * 16 + g;
                ah[i][0] = *(const uint32_t*)&As[ r0      * SRW + kk];
                ah[i][1] = *(const uint32_t*)&As[(r0 + 8) * SRW + kk];
                ah[i][2] = *(const uint32_t*)&As[ r0      * SRW + kk + 8];
                ah[i][3] = *(const uint32_t*)&As[(r0 + 8) * SRW + kk + 8];
            }
#pragma unroll
            for (int j = 0; j < 4; ++j) {
                int n0 = wn + j * 8 + g;
                uint32_t bh0 = *(const uint32_t*)&Bs[n0 * SRW + kk];
                uint32_t bh1 = *(const uint32_t*)&Bs[n0 * SRW + kk + 8];
#pragma unroll
                for (int i = 0; i < 4; ++i)
                    mma_f16(acc[i][j], ah[i], bh0, bh1);
            }
        }
        cbuf = (cbuf == NSTAGE - 1) ? 0 : cbuf + 1;
        ibuf = (ibuf == NSTAGE - 1) ? 0 : ibuf + 1;
    }
}

__global__ __launch_bounds__(256, 2) void gemm1_kernel() {
    extern __shared__ __half smdyn[];
    float acc[4][4][4];
#pragma unroll
    for (int i = 0; i < 4; ++i)
#pragma unroll
        for (int j = 0; j < 4; ++j)
#pragma unroll
            for (int v = 0; v < 4; ++v) acc[i][j][v] = 0.f;

    gemm_1t_core(g_xh, g_wih, N1, KD, acc, smdyn);

    int tid = threadIdx.x, warp = tid >> 5, lane = tid & 31;
    int wm = (warp & 1) * 64, wn = (warp >> 1) * 32;
    int g = lane >> 2, tg = lane & 3;
    int bm = blockIdx.y * 128, bn = blockIdx.x * 128;
#pragma unroll
    for (int i = 0; i < 4; ++i) {
        int r0 = bm + wm + i * 16 + g;
#pragma unroll
        for (int j = 0; j < 4; ++j) {
            int col = bn + wn + j * 8 + tg * 2;
            *(__half2*)(g_u + (size_t)r0      * N1 + col) = __floats2half2_rn(acc[i][j][0], acc[i][j][1]);
            *(__half2*)(g_u + (size_t)(r0+8)  * N1 + col) = __floats2half2_rn(acc[i][j][2], acc[i][j][3]);
        }
    }
}

__global__ __launch_bounds__(256, 2) void gemm2_kernel(float* __restrict__ out) {
    extern __shared__ __half smdyn[];
    float acc[4][4][4];
#pragma unroll
    for (int i = 0; i < 4; ++i)
#pragma unroll
        for (int j = 0; j < 4; ++j)
#pragma unroll
            for (int v = 0; v < 4; ++v) acc[i][j][v] = 0.f;

    gemm_1t_core(g_yh, g_woh, KD, KD, acc, smdyn);

    int tid = threadIdx.x, warp = tid >> 5, lane = tid & 31;
    int wm = (warp & 1) * 64, wn = (warp >> 1) * 32;
    int g = lane >> 2, tg = lane & 3;
    int bm = blockIdx.y * 128, bn = blockIdx.x * 128;
#pragma unroll
    for (int i = 0; i < 4; ++i) {
        int r0 = bm + wm + i * 16 + g;
#pragma unroll
        for (int j = 0; j < 4; ++j) {
            int col = bn + wn + j * 8 + tg * 2;
            *(float2*)(out + (size_t)r0      * KD + col) = make_float2(acc[i][j][0], acc[i][j][1]);
            *(float2*)(out + (size_t)(r0+8)  * KD + col) = make_float2(acc[i][j][2], acc[i][j][3]);
        }
    }
}

// ---------------- Phase A: per-chunk local scan (u fp16, prefetched) --------
__global__ void scanA_kernel() {
    int d = blockIdx.x * 256 + threadIdx.x;
    int j = blockIdx.y, b = blockIdx.z;
    int ch0 = d * RANK;
    float2 a[RANK], bb[RANK], cc[RANK], s[RANK];
#pragma unroll
    for (int r = 0; r < RANK; ++r) {
        a[r] = g_ca[ch0 + r]; bb[r] = g_cb[ch0 + r]; cc[r] = g_cc[ch0 + r];
        s[r] = make_float2(0.f, 0.f);
    }
    int t0 = j * CL;
    const uint4* up = (const uint4*)(g_u + (size_t)(b * TLEN + t0) * N1 + d * (RANK * 2));
    float* yp = g_y + (size_t)(b * TLEN + t0) * D_MODEL + d;
    uint4 v = *up;
    for (int t = 0; t < CL; ++t) {
        up += N1 / 8;
        uint4 vn;
        if (t + 1 < CL) vn = *up;            // prefetch next before compute
        const __half2* ph = (const __half2*)&v;
        float y = 0.f;
#pragma unroll
        for (int r = 0; r < RANK; ++r) {
            float2 uc = __half22float2(ph[r]);
            float bur = bb[r].x * uc.x - bb[r].y * uc.y;
            float bui = bb[r].x * uc.y + bb[r].y * uc.x;
            float sr  = a[r].x * s[r].x - a[r].y * s[r].y + bur;
            float si  = a[r].x * s[r].y + a[r].y * s[r].x + bui;
            s[r] = make_float2(sr, si);
            y += cc[r].x * sr - cc[r].y * si;
        }
        *yp = y;
        yp += D_MODEL;
        v = vn;
    }
    float2* sp = g_Sloc + (size_t)(b * NCHUNK + j) * NCH + ch0;
#pragma unroll
    for (int r = 0; r < RANK; ++r) sp[r] = s[r];
}

// ---------------- Phase B: sequential carry combine across chunks ----------------
__global__ void scanB_kernel() {
    int idx = blockIdx.x * 256 + threadIdx.x;
    if (idx >= BATCH * NCH) return;
    int b = idx / NCH, ch = idx % NCH;
    float2 aL = g_aL[ch];
    float2 carry = make_float2(0.f, 0.f);
    for (int j = 0; j < NCHUNK; ++j) {
        g_carry[(size_t)(b * NCHUNK + j) * NCH + ch] = carry;
        float2 S = g_Sloc[(size_t)(b * NCHUNK + j) * NCH + ch];
        carry = make_float2(aL.x * carry.x - aL.y * carry.y + S.x,
                            aL.x * carry.y + aL.y * carry.x + S.y);
    }
}

// ---------------- Phase C: y += Re(c*a^p*carry) -> fp16 yh (all chunks) -----
__global__ void scanC_kernel() {
    int d = blockIdx.x * 256 + threadIdx.x;
    int j = blockIdx.y, b = blockIdx.z;       // j=0: carry=0 -> pure round
    int ch0 = d * RANK;
    float2 a[RANK], w[RANK];
#pragma unroll
    for (int r = 0; r < RANK; ++r) {
        a[r] = g_ca[ch0 + r];
        float2 carry = g_carry[(size_t)(b * NCHUNK + j) * NCH + ch0 + r];
        float2 c = g_cc[ch0 + r];
        w[r] = make_float2(c.x * carry.x - c.y * carry.y,
                           c.x * carry.y + c.y * carry.x);
    }
    int t0 = j * CL;
    size_t idx = (size_t)(b * TLEN + t0) * D_MODEL + d;
    for (int t = 0; t < CL; ++t) {
        float corr = 0.f;
#pragma unroll
        for (int r = 0; r < RANK; ++r) {
            w[r] = make_float2(w[r].x * a[r].x - w[r].y * a[r].y,
                               w[r].x * a[r].y + w[r].y * a[r].x);
            corr += w[r].x;
        }
        g_yh[idx] = __float2half(g_y[idx] + corr);
        idx += D_MODEL;
    }
}

// ---------------- launch (no device symbols passed from host; no guards) ----
extern "C" void kernel_launch(void* const* d_in, const int* in_sizes, int n_in,
                              void* d_out, int out_size) {
    const float* x    = (const float*)d_in[0];
    const float* nw   = (const float*)d_in[1];
    const float* Win  = (const float*)d_in[2];
    const float* Wout = (const float*)d_in[3];
    const float* ap   = (const float*)d_in[4];
    const float* bp   = (const float*)d_in[5];
    const float* cp   = (const float*)d_in[6];
    float* out = (float*)d_out;

    // idempotent, host-side, capture-legal; called every time (no static guard)
    cudaFuncSetAttribute(gemm1_kernel, cudaFuncAttributeMaxDynamicSharedMemorySize, GEMM_SMEM);
    cudaFuncSetAttribute(gemm2_kernel, cudaFuncAttributeMaxDynamicSharedMemorySize, GEMM_SMEM);

    coef_kernel<<<(NCH + 255) / 256, 256>>>(ap, bp, cp);
    round_w_kernel<<<(N1 * KD + KD * KD + 255) / 256, 256>>>(Win, Wout);
    rmsnorm_kernel<<<MROWS, 256>>>(x, nw);
    gemm1_kernel<<<dim3(N1 / 128, MROWS / 128), 256, GEMM_SMEM>>>();
    scanA_kernel<<<dim3(D_MODEL / 256, NCHUNK, BATCH), 256>>>();
    scanB_kernel<<<(BATCH * NCH + 255) / 256, 256>>>();
    scanC_kernel<<<dim3(D_MODEL / 256, NCHUNK, BATCH), 256>>>();
    gemm2_kernel<<<dim3(KD / 128, MROWS / 128), 256, GEMM_SMEM>>>(out);
}

// round 15
// speedup vs baseline: 4.5267x; 1.1454x over previous
#include <cuda_runtime.h>
#include <cuda_fp16.h>
#include <math.h>
#include <stdint.h>

#define D_MODEL 768
#define RANK 4
#define BATCH 2
#define TLEN 2048
#define MROWS (BATCH*TLEN)          // 4096
#define N1 (D_MODEL*RANK*2)         // 6144
#define KD D_MODEL                  // 768
#define NCH (D_MODEL*RANK)          // 3072
#define NCHUNK 128
#define CL (TLEN/NCHUNK)            // 16

// ---------------- scratch (static __device__, no allocations) ----------------
__device__ __half g_xh [MROWS*KD];                    // x rounded fp16
__device__ __half g_wih[N1*KD];                       // W_in  rounded fp16
__device__ __half g_woh[KD*KD];                       // W_out rounded fp16
__device__ __half g_yh [MROWS*KD];                    // y rounded fp16
__device__ __half g_u[MROWS*N1];                      // u in fp16 (48 MB)
__device__ float  g_y[MROWS*KD];
__device__ float2 g_ca[NCH], g_cb[NCH], g_cc[NCH], g_aL[NCH];
__device__ float2 g_Sloc [BATCH*NCHUNK*NCH];
__device__ float2 g_carry[BATCH*NCHUNK*NCH];

// ---------------- coefficient precompute ----------------
__global__ void coef_kernel(const float* __restrict__ ap,
                            const float* __restrict__ bp,
                            const float* __restrict__ cp) {
    int i = blockIdx.x * blockDim.x + threadIdx.x;
    if (i >= NCH) return;
    float2 a = make_float2(tanhf(ap[2*i]) * 0.97f, tanhf(ap[2*i+1]) * 0.97f);
    float2 b = make_float2(tanhf(bp[2*i]),         tanhf(bp[2*i+1]));
    float2 c = make_float2(tanhf(cp[2*i]),         tanhf(cp[2*i+1]));
    g_ca[i] = a; g_cb[i] = b; g_cc[i] = c;
    float2 p = a;
    for (int k = 1; k < CL; ++k)
        p = make_float2(p.x*a.x - p.y*a.y, p.x*a.y + p.y*a.x);
    g_aL[i] = p;
}

// ---------------- fp16 rounding of both weight matrices (one launch) --------
__global__ void round_w_kernel(const float* __restrict__ win,
                               const float* __restrict__ wout) {
    int i = blockIdx.x * 256 + threadIdx.x;
    if (i < N1*KD) {
        g_wih[i] = __float2half(win[i]);
    } else if (i < N1*KD + KD*KD) {
        int j = i - N1*KD;
        g_woh[j] = __float2half(wout[j]);
    }
}

// ---------------- RMSNorm -> fp16 ----------------
__global__ void rmsnorm_kernel(const float* __restrict__ x,
                               const float* __restrict__ w) {
    int row = blockIdx.x;
    const float* xr = x + (size_t)row * KD;
    float s = 0.f;
    for (int k = threadIdx.x; k < KD; k += 256) { float v = xr[k]; s += v * v; }
    __shared__ float red[256];
    red[threadIdx.x] = s; __syncthreads();
    for (int off = 128; off > 0; off >>= 1) {
        if (threadIdx.x < off) red[threadIdx.x] += red[threadIdx.x + off];
        __syncthreads();
    }
    float scale = rsqrtf(red[0] * (1.0f / KD) + 1e-6f);
    for (int k = threadIdx.x; k < KD; k += 256)
        g_xh[(size_t)row*KD + k] = __float2half(xr[k] * scale * w[k]);
}

// ============================================================================
// fp16 1-term GEMM, fp32 accum, mma.m16n8k16.  BM=BN=128, BK=32, 256 threads,
// warp grid 2x4, warp tile 64x32.  3-stage cp.async pipeline, ONE barrier per
// k-tile, operand loads via ldmatrix.x4 (12 LDSM/tile vs 48 LDS).  lb(256,2).
// ============================================================================
#define SRW 40                       // smem row stride in fp16 (80B)
#define SSTG (2 * 128 * SRW)         // halves per stage (A tile + B tile)
#define NSTAGE 3
#define GEMM_SMEM (NSTAGE * SSTG * 2)   // 61440 bytes

__device__ __forceinline__ void mma_f16(float* c, const uint32_t* a,
                                        uint32_t b0, uint32_t b1) {
    asm volatile(
        "mma.sync.aligned.m16n8k16.row.col.f32.f16.f16.f32 "
        "{%0,%1,%2,%3}, {%4,%5,%6,%7}, {%8,%9}, {%0,%1,%2,%3};\n"
        : "+f"(c[0]), "+f"(c[1]), "+f"(c[2]), "+f"(c[3])
        : "r"(a[0]), "r"(a[1]), "r"(a[2]), "r"(a[3]), "r"(b0), "r"(b1));
}
__device__ __forceinline__ void cpa16(uint32_t s, const void* g) {
    asm volatile("cp.async.cg.shared.global [%0], [%1], 16;\n" :: "r"(s), "l"(g));
}
__device__ __forceinline__ void ldsm4(uint32_t* r, uint32_t a) {
    asm volatile("ldmatrix.sync.aligned.m8n8.x4.shared.b16 {%0,%1,%2,%3}, [%4];"
                 : "=r"(r[0]), "=r"(r[1]), "=r"(r[2]), "=r"(r[3]) : "r"(a));
}

__device__ __forceinline__ void gemm_1t_core(
    const __half* __restrict__ Ah, const __half* __restrict__ Bh,
    int N, int K, float acc[4][4][4], __half* smbase)
{
    int tid  = threadIdx.x;
    int bm   = blockIdx.y * 128;
    int bn   = blockIdx.x * 128;
    int warp = tid >> 5, lane = tid & 31;
    int wm   = (warp & 1) * 64;
    int wn   = (warp >> 1) * 32;

    int row  = tid >> 1;
    int half = (tid & 1) * 16;
    const __half* gA = Ah + (size_t)(bm + row) * K + half;
    const __half* gB = Bh + (size_t)(bn + row) * K + half;
    uint32_t smb = (uint32_t)__cvta_generic_to_shared(smbase);
    uint32_t sA = smb + (uint32_t)(row * SRW + half) * 2u;
    uint32_t sB = sA + 128u * SRW * 2u;

    // ldmatrix lane offsets (bytes), ks=0 base:
    // A fragment i: lanes 0-7 rows wm+0..7 col 0 | 8-15 rows +8 | 16-23 rows 0..7 col+8 | 24-31 rows +8 col+8
    uint32_t aoff = ((uint32_t)(wm + (lane & 15)) * SRW + (uint32_t)(lane >> 4) * 8u) * 2u;
    // B pair p (j=2p,2p+1): lanes 0-7 n=wn..+7 col0 | 8-15 same rows col+8 | 16-23 n+8 col0 | 24-31 n+8 col+8
    uint32_t boff = ((uint32_t)(wn + (lane >> 4) * 8 + (lane & 7)) * SRW
                     + (uint32_t)((lane >> 3) & 1) * 8u) * 2u;

    const int nt = K / 32;             // 24
#pragma unroll
    for (int st = 0; st < 2; ++st) {
        uint32_t off = (uint32_t)st * SSTG * 2u;
        int k0 = st * 32;
        cpa16(sA + off,      gA + k0);
        cpa16(sA + off + 16, gA + k0 + 8);
        cpa16(sB + off,      gB + k0);
        cpa16(sB + off + 16, gB + k0 + 8);
        asm volatile("cp.async.commit_group;\n");
    }

    int cbuf = 0, ibuf = 2;
    for (int t = 0; t < nt; ++t) {
        asm volatile("cp.async.wait_group 1;\n");
        __syncthreads();

        if (t + 2 < nt) {
            uint32_t off = (uint32_t)ibuf * SSTG * 2u;
            int k0 = (t + 2) * 32;
            cpa16(sA + off,      gA + k0);
            cpa16(sA + off + 16, gA + k0 + 8);
            cpa16(sB + off,      gB + k0);
            cpa16(sB + off + 16, gB + k0 + 8);
        }
        asm volatile("cp.async.commit_group;\n");

        uint32_t As_u = smb + (uint32_t)cbuf * SSTG * 2u;
        uint32_t Bs_u = As_u + 128u * SRW * 2u;
#pragma unroll
        for (int ks = 0; ks < 2; ++ks) {
            uint32_t kso = (uint32_t)ks * 32u;        // 16 halves
            uint32_t ah[4][4];
#pragma unroll
            for (int i = 0; i < 4; ++i)
                ldsm4(ah[i], As_u + aoff + (uint32_t)i * 16u * SRW * 2u + kso);
            uint32_t bf[2][4];
#pragma unroll
            for (int p = 0; p < 2; ++p)
                ldsm4(bf[p], Bs_u + boff + (uint32_t)p * 16u * SRW * 2u + kso);
#pragma unroll
            for (int j = 0; j < 4; ++j) {
                uint32_t bh0 = bf[j >> 1][(j & 1) * 2];
                uint32_t bh1 = bf[j >> 1][(j & 1) * 2 + 1];
#pragma unroll
                for (int i = 0; i < 4; ++i)
                    mma_f16(acc[i][j], ah[i], bh0, bh1);
            }
        }
        cbuf = (cbuf == NSTAGE - 1) ? 0 : cbuf + 1;
        ibuf = (ibuf == NSTAGE - 1) ? 0 : ibuf + 1;
    }
}

__global__ __launch_bounds__(256, 2) void gemm1_kernel() {
    extern __shared__ __half smdyn[];
    float acc[4][4][4];
#pragma unroll
    for (int i = 0; i < 4; ++i)
#pragma unroll
        for (int j = 0; j < 4; ++j)
#pragma unroll
            for (int v = 0; v < 4; ++v) acc[i][j][v] = 0.f;

    gemm_1t_core(g_xh, g_wih, N1, KD, acc, smdyn);

    int tid = threadIdx.x, warp = tid >> 5, lane = tid & 31;
    int wm = (warp & 1) * 64, wn = (warp >> 1) * 32;
    int g = lane >> 2, tg = lane & 3;
    int bm = blockIdx.y * 128, bn = blockIdx.x * 128;
#pragma unroll
    for (int i = 0; i < 4; ++i) {
        int r0 = bm + wm + i * 16 + g;
#pragma unroll
        for (int j = 0; j < 4; ++j) {
            int col = bn + wn + j * 8 + tg * 2;
            *(__half2*)(g_u + (size_t)r0      * N1 + col) = __floats2half2_rn(acc[i][j][0], acc[i][j][1]);
            *(__half2*)(g_u + (size_t)(r0+8)  * N1 + col) = __floats2half2_rn(acc[i][j][2], acc[i][j][3]);
        }
    }
}

__global__ __launch_bounds__(256, 2) void gemm2_kernel(float* __restrict__ out) {
    extern __shared__ __half smdyn[];
    float acc[4][4][4];
#pragma unroll
    for (int i = 0; i < 4; ++i)
#pragma unroll
        for (int j = 0; j < 4; ++j)
#pragma unroll
            for (int v = 0; v < 4; ++v) acc[i][j][v] = 0.f;

    gemm_1t_core(g_yh, g_woh, KD, KD, acc, smdyn);

    int tid = threadIdx.x, warp = tid >> 5, lane = tid & 31;
    int wm = (warp & 1) * 64, wn = (warp >> 1) * 32;
    int g = lane >> 2, tg = lane & 3;
    int bm = blockIdx.y * 128, bn = blockIdx.x * 128;
#pragma unroll
    for (int i = 0; i < 4; ++i) {
        int r0 = bm + wm + i * 16 + g;
#pragma unroll
        for (int j = 0; j < 4; ++j) {
            int col = bn + wn + j * 8 + tg * 2;
            *(float2*)(out + (size_t)r0      * KD + col) = make_float2(acc[i][j][0], acc[i][j][1]);
            *(float2*)(out + (size_t)(r0+8)  * KD + col) = make_float2(acc[i][j][2], acc[i][j][3]);
        }
    }
}

// ---------------- Phase A: per-chunk local scan (u fp16, prefetched) --------
__global__ void scanA_kernel() {
    int d = blockIdx.x * 256 + threadIdx.x;
    int j = blockIdx.y, b = blockIdx.z;
    int ch0 = d * RANK;
    float2 a[RANK], bb[RANK], cc[RANK], s[RANK];
#pragma unroll
    for (int r = 0; r < RANK; ++r) {
        a[r] = g_ca[ch0 + r]; bb[r] = g_cb[ch0 + r]; cc[r] = g_cc[ch0 + r];
        s[r] = make_float2(0.f, 0.f);
    }
    int t0 = j * CL;
    const uint4* up = (const uint4*)(g_u + (size_t)(b * TLEN + t0) * N1 + d * (RANK * 2));
    float* yp = g_y + (size_t)(b * TLEN + t0) * D_MODEL + d;
    uint4 v = *up;
    for (int t = 0; t < CL; ++t) {
        up += N1 / 8;
        uint4 vn;
        if (t + 1 < CL) vn = *up;
        const __half2* ph = (const __half2*)&v;
        float y = 0.f;
#pragma unroll
        for (int r = 0; r < RANK; ++r) {
            float2 uc = __half22float2(ph[r]);
            float bur = bb[r].x * uc.x - bb[r].y * uc.y;
            float bui = bb[r].x * uc.y + bb[r].y * uc.x;
            float sr  = a[r].x * s[r].x - a[r].y * s[r].y + bur;
            float si  = a[r].x * s[r].y + a[r].y * s[r].x + bui;
            s[r] = make_float2(sr, si);
            y += cc[r].x * sr - cc[r].y * si;
        }
        *yp = y;
        yp += D_MODEL;
        v = vn;
    }
    float2* sp = g_Sloc + (size_t)(b * NCHUNK + j) * NCH + ch0;
#pragma unroll
    for (int r = 0; r < RANK; ++r) sp[r] = s[r];
}

// ---------------- Phase B: sequential carry combine across chunks ----------------
__global__ void scanB_kernel() {
    int idx = blockIdx.x * 256 + threadIdx.x;
    if (idx >= BATCH * NCH) return;
    int b = idx / NCH, ch = idx % NCH;
    float2 aL = g_aL[ch];
    float2 carry = make_float2(0.f, 0.f);
    for (int j = 0; j < NCHUNK; ++j) {
        g_carry[(size_t)(b * NCHUNK + j) * NCH + ch] = carry;
        float2 S = g_Sloc[(size_t)(b * NCHUNK + j) * NCH + ch];
        carry = make_float2(aL.x * carry.x - aL.y * carry.y + S.x,
                            aL.x * carry.y + aL.y * carry.x + S.y);
    }
}

// ---------------- Phase C: y += Re(c*a^p*carry) -> fp16 yh (all chunks) -----
__global__ void scanC_kernel() {
    int d = blockIdx.x * 256 + threadIdx.x;
    int j = blockIdx.y, b = blockIdx.z;
    int ch0 = d * RANK;
    float2 a[RANK], w[RANK];
#pragma unroll
    for (int r = 0; r < RANK; ++r) {
        a[r] = g_ca[ch0 + r];
        float2 carry = g_carry[(size_t)(b * NCHUNK + j) * NCH + ch0 + r];
        float2 c = g_cc[ch0 + r];
        w[r] = make_float2(c.x * carry.x - c.y * carry.y,
                           c.x * carry.y + c.y * carry.x);
    }
    int t0 = j * CL;
    size_t idx = (size_t)(b * TLEN + t0) * D_MODEL + d;
    for (int t = 0; t < CL; ++t) {
        float corr = 0.f;
#pragma unroll
        for (int r = 0; r < RANK; ++r) {
            w[r] = make_float2(w[r].x * a[r].x - w[r].y * a[r].y,
                               w[r].x * a[r].y + w[r].y * a[r].x);
            corr += w[r].x;
        }
        g_yh[idx] = __float2half(g_y[idx] + corr);
        idx += D_MODEL;
    }
}

// ---------------- launch (no device symbols passed from host; no guards) ----
extern "C" void kernel_launch(void* const* d_in, const int* in_sizes, int n_in,
                              void* d_out, int out_size) {
    const float* x    = (const float*)d_in[0];
    const float* nw   = (const float*)d_in[1];
    const float* Win  = (const float*)d_in[2];
    const float* Wout = (const float*)d_in[3];
    const float* ap   = (const float*)d_in[4];
    const float* bp   = (const float*)d_in[5];
    const float* cp   = (const float*)d_in[6];
    float* out = (float*)d_out;

    cudaFuncSetAttribute(gemm1_kernel, cudaFuncAttributeMaxDynamicSharedMemorySize, GEMM_SMEM);
    cudaFuncSetAttribute(gemm2_kernel, cudaFuncAttributeMaxDynamicSharedMemorySize, GEMM_SMEM);

    coef_kernel<<<(NCH + 255) / 256, 256>>>(ap, bp, cp);
    round_w_kernel<<<(N1 * KD + KD * KD + 255) / 256, 256>>>(Win, Wout);
    rmsnorm_kernel<<<MROWS, 256>>>(x, nw);
    gemm1_kernel<<<dim3(N1 / 128, MROWS / 128), 256, GEMM_SMEM>>>();
    scanA_kernel<<<dim3(D_MODEL / 256, NCHUNK, BATCH), 256>>>();
    scanB_kernel<<<(BATCH * NCH + 255) / 256, 256>>>();
    scanC_kernel<<<dim3(D_MODEL / 256, NCHUNK, BATCH), 256>>>();
    gemm2_kernel<<<dim3(KD / 128, MROWS / 128), 256, GEMM_SMEM>>>(out);
}